// round 1
// baseline (speedup 1.0000x reference)
#include <cuda_runtime.h>
#include <cstdint>
#include <cstddef>

// ---------------- problem constants ----------------
#define B_TOTAL 131072
#define D_INPUT 385
#define D_H     192
#define NQ      1000
#define NHEADS  2000
#define NC      16

// ---------------- scratch (device globals: allocation-free) ----------------
__device__ float g_feat[(size_t)B_TOTAL * D_H];   // trunk output, ~100 MB
__device__ int   g_cnt[NHEADS];
__device__ int   g_off[NHEADS + 1];
__device__ int   g_cur[NHEADS];
__device__ int   g_order[B_TOTAL];

// ---------------- helpers ----------------
__device__ __forceinline__ float to_tf32(float x) {
    uint32_t u;
    asm("cvt.rna.tf32.f32 %0, %1;" : "=r"(u) : "f"(x));
    return __uint_as_float(u);
}

__device__ __forceinline__ void mma8(float c[4], const float a[4], const float b[2]) {
    asm volatile(
        "mma.sync.aligned.m16n8k8.row.col.f32.tf32.tf32.f32 "
        "{%0,%1,%2,%3}, {%4,%5,%6,%7}, {%8,%9}, {%0,%1,%2,%3};\n"
        : "+f"(c[0]), "+f"(c[1]), "+f"(c[2]), "+f"(c[3])
        : "r"(__float_as_uint(a[0])), "r"(__float_as_uint(a[1])),
          "r"(__float_as_uint(a[2])), "r"(__float_as_uint(a[3])),
          "r"(__float_as_uint(b[0])), "r"(__float_as_uint(b[1])));
}

// ---------------- fused trunk: feat = relu(relu(x@W1+b1)@W2+b2) ----------------
// CTA tile: 128 rows x 192 cols. 8 warps (4 M-splits x 2 N-splits), warp tile 32x96.
#define TM   128
#define TKC  32
#define ASTR 33    // A smem row stride (pad)
#define BSTR 200   // B smem row stride (192 padded; 200 % 32 == 8 -> conflict-free B frags)
#define HSTR 200
#define SMEM_FLOATS (TM * ASTR + TKC * BSTR + TM * HSTR)
#define SMEM_BYTES  (SMEM_FLOATS * 4)

__global__ void __launch_bounds__(256, 1) trunk_kernel(
    const float* __restrict__ x,
    const float* __restrict__ W1, const float* __restrict__ b1,
    const float* __restrict__ W2, const float* __restrict__ b2)
{
    extern __shared__ float sm[];
    float* As = sm;                       // [128][33]
    float* Bs = sm + TM * ASTR;           // [32][200]
    float* Hs = Bs + TKC * BSTR;          // [128][200]

    const int tid  = threadIdx.x;
    const int lane = tid & 31;
    const int wid  = tid >> 5;
    const int wm   = wid & 3;             // 0..3 -> rows wm*32
    const int wn   = wid >> 2;            // 0..1 -> cols wn*96
    const int gid  = lane >> 2;           // 0..7
    const int tig  = lane & 3;            // 0..3
    const int row0 = blockIdx.x * TM;

    float c[2][12][4];
    #pragma unroll
    for (int mt = 0; mt < 2; mt++)
        #pragma unroll
        for (int nt = 0; nt < 12; nt++)
            #pragma unroll
            for (int q = 0; q < 4; q++) c[mt][nt][q] = 0.f;

    // ---------- stage 1: h = relu(x @ W1 + b1) ----------
    const int KT1 = (D_INPUT + TKC - 1) / TKC;   // 13 (last partial: zero fill)
    for (int kt = 0; kt < KT1; kt++) {
        const int k0 = kt * TKC;
        // load x tile [128 x 32] (coalesced: 32 consecutive k per warp-row)
        {
            const int col = tid & 31, rbase = tid >> 5;
            const int k = k0 + col;
            #pragma unroll
            for (int i = 0; i < 16; i++) {
                const int r = rbase + i * 8;
                float v = (k < D_INPUT) ? x[(size_t)(row0 + r) * D_INPUT + k] : 0.f;
                As[r * ASTR + col] = to_tf32(v);
            }
        }
        // load W1 tile [32 x 192]
        for (int i = tid; i < TKC * D_H; i += 256) {
            const int kr = i / D_H, n = i % D_H;
            const int k = k0 + kr;
            float v = (k < D_INPUT) ? W1[(size_t)k * D_H + n] : 0.f;
            Bs[kr * BSTR + n] = to_tf32(v);
        }
        __syncthreads();
        #pragma unroll
        for (int ks = 0; ks < 4; ks++) {
            const int kk = ks * 8;
            float a[2][4];
            #pragma unroll
            for (int mt = 0; mt < 2; mt++) {
                const int r = wm * 32 + mt * 16 + gid;
                a[mt][0] = As[r * ASTR + kk + tig];
                a[mt][1] = As[(r + 8) * ASTR + kk + tig];
                a[mt][2] = As[r * ASTR + kk + tig + 4];
                a[mt][3] = As[(r + 8) * ASTR + kk + tig + 4];
            }
            float b[12][2];
            #pragma unroll
            for (int nt = 0; nt < 12; nt++) {
                const int n = wn * 96 + nt * 8 + gid;
                b[nt][0] = Bs[(kk + tig) * BSTR + n];
                b[nt][1] = Bs[(kk + tig + 4) * BSTR + n];
            }
            #pragma unroll
            for (int mt = 0; mt < 2; mt++)
                #pragma unroll
                for (int nt = 0; nt < 12; nt++)
                    mma8(c[mt][nt], a[mt], b[nt]);
        }
        __syncthreads();
    }
    // epilogue 1: Hs = tf32(relu(c + b1))
    #pragma unroll
    for (int mt = 0; mt < 2; mt++) {
        const int r = wm * 32 + mt * 16 + gid;
        #pragma unroll
        for (int nt = 0; nt < 12; nt++) {
            const int n = wn * 96 + nt * 8 + 2 * tig;
            const float bb0 = __ldg(&b1[n]), bb1 = __ldg(&b1[n + 1]);
            Hs[r * HSTR + n]           = to_tf32(fmaxf(c[mt][nt][0] + bb0, 0.f));
            Hs[r * HSTR + n + 1]       = to_tf32(fmaxf(c[mt][nt][1] + bb1, 0.f));
            Hs[(r + 8) * HSTR + n]     = to_tf32(fmaxf(c[mt][nt][2] + bb0, 0.f));
            Hs[(r + 8) * HSTR + n + 1] = to_tf32(fmaxf(c[mt][nt][3] + bb1, 0.f));
        }
    }
    __syncthreads();

    // ---------- stage 2: feat = relu(h @ W2 + b2) ----------
    #pragma unroll
    for (int mt = 0; mt < 2; mt++)
        #pragma unroll
        for (int nt = 0; nt < 12; nt++)
            #pragma unroll
            for (int q = 0; q < 4; q++) c[mt][nt][q] = 0.f;

    for (int kt = 0; kt < D_H / TKC; kt++) {     // 6
        const int k0 = kt * TKC;
        for (int i = tid; i < TKC * D_H; i += 256) {
            const int kr = i / D_H, n = i % D_H;
            Bs[kr * BSTR + n] = to_tf32(W2[(size_t)(k0 + kr) * D_H + n]);
        }
        __syncthreads();
        #pragma unroll
        for (int ks = 0; ks < 4; ks++) {
            const int kk = k0 + ks * 8;
            float a[2][4];
            #pragma unroll
            for (int mt = 0; mt < 2; mt++) {
                const int r = wm * 32 + mt * 16 + gid;
                a[mt][0] = Hs[r * HSTR + kk + tig];
                a[mt][1] = Hs[(r + 8) * HSTR + kk + tig];
                a[mt][2] = Hs[r * HSTR + kk + tig + 4];
                a[mt][3] = Hs[(r + 8) * HSTR + kk + tig + 4];
            }
            float b[12][2];
            #pragma unroll
            for (int nt = 0; nt < 12; nt++) {
                const int n = wn * 96 + nt * 8 + gid;
                b[nt][0] = Bs[(ks * 8 + tig) * BSTR + n];
                b[nt][1] = Bs[(ks * 8 + tig + 4) * BSTR + n];
            }
            #pragma unroll
            for (int mt = 0; mt < 2; mt++)
                #pragma unroll
                for (int nt = 0; nt < 12; nt++)
                    mma8(c[mt][nt], a[mt], b[nt]);
        }
        __syncthreads();
    }
    // epilogue 2: g_feat = relu(c + b2)   (full fp32)
    #pragma unroll
    for (int mt = 0; mt < 2; mt++) {
        const int r = wm * 32 + mt * 16 + gid;
        #pragma unroll
        for (int nt = 0; nt < 12; nt++) {
            const int n = wn * 96 + nt * 8 + 2 * tig;
            const float bb0 = __ldg(&b2[n]), bb1 = __ldg(&b2[n + 1]);
            g_feat[(size_t)(row0 + r) * D_H + n]         = fmaxf(c[mt][nt][0] + bb0, 0.f);
            g_feat[(size_t)(row0 + r) * D_H + n + 1]     = fmaxf(c[mt][nt][1] + bb1, 0.f);
            g_feat[(size_t)(row0 + r + 8) * D_H + n]     = fmaxf(c[mt][nt][2] + bb0, 0.f);
            g_feat[(size_t)(row0 + r + 8) * D_H + n + 1] = fmaxf(c[mt][nt][3] + bb1, 0.f);
        }
    }
}

// ---------------- binning: histogram -> scan -> scatter ----------------
__global__ void zero_kernel() {
    int i = blockIdx.x * blockDim.x + threadIdx.x;
    if (i < NHEADS) g_cnt[i] = 0;
}

__global__ void hist_kernel(const int* __restrict__ qid, const int* __restrict__ cor) {
    int b = blockIdx.x * blockDim.x + threadIdx.x;
    if (b < B_TOTAL) atomicAdd(&g_cnt[qid[b] + cor[b] * NQ], 1);
}

__global__ void scan_kernel() {   // single block of 1024, Hillis-Steele over 2048
    __shared__ int s[2048];
    const int t = threadIdx.x;
    s[t]        = (t < NHEADS) ? g_cnt[t] : 0;
    s[t + 1024] = (t + 1024 < NHEADS) ? g_cnt[t + 1024] : 0;
    __syncthreads();
    for (int d = 1; d < 2048; d <<= 1) {
        int v0 = s[t], v1 = s[t + 1024];
        int a0 = (t >= d) ? s[t - d] : 0;
        int a1 = (t + 1024 >= d) ? s[t + 1024 - d] : 0;
        __syncthreads();
        s[t] = v0 + a0;
        s[t + 1024] = v1 + a1;
        __syncthreads();
    }
    if (t < NHEADS)          { int e = (t == 0) ? 0 : s[t - 1]; g_off[t] = e; g_cur[t] = e; }
    if (t + 1024 < NHEADS)   { int e = s[t + 1023];             g_off[t + 1024] = e; g_cur[t + 1024] = e; }
    if (t == 0) g_off[NHEADS] = s[NHEADS - 1];
}

__global__ void scatter_kernel(const int* __restrict__ qid, const int* __restrict__ cor) {
    int b = blockIdx.x * blockDim.x + threadIdx.x;
    if (b < B_TOTAL) {
        int h = qid[b] + cor[b] * NQ;
        int p = atomicAdd(&g_cur[h], 1);
        g_order[p] = b;
    }
}

// ---------------- routed heads: one CTA per head group ----------------
// thread t: class c = t&15, k-chunk j = t>>4 (12 elems); Wq held in registers.
__global__ void __launch_bounds__(256) heads_kernel(
    const float* __restrict__ Wh, const float* __restrict__ bh, float* __restrict__ out)
{
    const int g = blockIdx.x;
    const int t = threadIdx.x;
    const int c = t & 15, j = t >> 4;

    __shared__ float s_feat[D_H];
    __shared__ float s_part[256];
    __shared__ float s_bq[NC];

    float w[12];
    const float* wp = Wh + ((size_t)g * NC + c) * D_H + j * 12;
    #pragma unroll
    for (int u = 0; u < 12; u++) w[u] = wp[u];
    if (t < NC) s_bq[t] = bh[g * NC + t];

    const int start = g_off[g], end = g_off[g + 1];

    float nxt = 0.f;
    if (start < end && t < D_H) nxt = g_feat[(size_t)g_order[start] * D_H + t];
    __syncthreads();

    for (int s = start; s < end; s++) {
        if (t < D_H) s_feat[t] = nxt;
        __syncthreads();
        if (s + 1 < end && t < D_H)              // prefetch next sample's feat
            nxt = g_feat[(size_t)g_order[s + 1] * D_H + t];
        float p = 0.f;
        const float* f = s_feat + j * 12;
        #pragma unroll
        for (int u = 0; u < 12; u++) p += w[u] * f[u];
        s_part[t] = p;
        __syncthreads();
        if (t < NC) {
            float sum = s_bq[t];
            #pragma unroll
            for (int jj = 0; jj < 16; jj++) sum += s_part[t + 16 * jj];
            out[(size_t)g_order[s] * NC + t] = sum;
        }
        __syncthreads();
    }
}

// ---------------- launch ----------------
extern "C" void kernel_launch(void* const* d_in, const int* in_sizes, int n_in,
                              void* d_out, int out_size) {
    const float* x   = (const float*)d_in[0];
    const int*   qid = (const int*)d_in[1];
    const int*   cor = (const int*)d_in[2];
    const float* W1  = (const float*)d_in[3];
    const float* b1  = (const float*)d_in[4];
    const float* W2  = (const float*)d_in[5];
    const float* b2  = (const float*)d_in[6];
    const float* Wh  = (const float*)d_in[7];
    const float* bh  = (const float*)d_in[8];
    float* out = (float*)d_out;

    cudaFuncSetAttribute(trunk_kernel, cudaFuncAttributeMaxDynamicSharedMemorySize, SMEM_BYTES);

    trunk_kernel<<<B_TOTAL / TM, 256, SMEM_BYTES>>>(x, W1, b1, W2, b2);
    zero_kernel<<<(NHEADS + 255) / 256, 256>>>();
    hist_kernel<<<(B_TOTAL + 255) / 256, 256>>>(qid, cor);
    scan_kernel<<<1, 1024>>>();
    scatter_kernel<<<(B_TOTAL + 255) / 256, 256>>>(qid, cor);
    heads_kernel<<<NHEADS, 256>>>(Wh, bh, out);
}

// round 3
// speedup vs baseline: 1.5154x; 1.5154x over previous
#include <cuda_runtime.h>
#include <cstdint>
#include <cstddef>

// ---------------- problem constants ----------------
#define B_TOTAL 131072
#define D_INPUT 385
#define D_H     192
#define NQ      1000
#define NHEADS  2000
#define NC      16

#define KPAD1   416            // 13 chunks of 32
#define NCH1    13
#define NCH2    6
#define P36     36             // staging pitch (4 mod 32 -> conflict-free frags)

// ---------------- scratch (device globals: allocation-free) ----------------
__device__ float g_h[(size_t)B_TOTAL * D_H];      // hidden, tf32-rounded, ~100 MB
__device__ float g_feat[(size_t)B_TOTAL * D_H];   // trunk output, ~100 MB
__device__ float g_W1T[D_H * KPAD1];              // W1^T, tf32-rounded, zero-padded
__device__ float g_W2T[D_H * D_H];                // W2^T, tf32-rounded
__device__ int   g_cnt[NHEADS];
__device__ int   g_off[NHEADS + 1];
__device__ int   g_cur[NHEADS];
__device__ int   g_order[B_TOTAL];

// ---------------- helpers ----------------
__device__ __forceinline__ float to_tf32(float x) {
    uint32_t u;
    asm("cvt.rna.tf32.f32 %0, %1;" : "=r"(u) : "f"(x));
    return __uint_as_float(u);
}

__device__ __forceinline__ void mma8(float c[4], const float a[4], const float b[2]) {
    asm volatile(
        "mma.sync.aligned.m16n8k8.row.col.f32.tf32.tf32.f32 "
        "{%0,%1,%2,%3}, {%4,%5,%6,%7}, {%8,%9}, {%0,%1,%2,%3};\n"
        : "+f"(c[0]), "+f"(c[1]), "+f"(c[2]), "+f"(c[3])
        : "r"(__float_as_uint(a[0])), "r"(__float_as_uint(a[1])),
          "r"(__float_as_uint(a[2])), "r"(__float_as_uint(a[3])),
          "r"(__float_as_uint(b[0])), "r"(__float_as_uint(b[1])));
}

// ---------------- prep: W1 -> W1^T (tf32, padded), W2 -> W2^T (tf32) ----------------
__global__ void prep_kernel(const float* __restrict__ W1, const float* __restrict__ W2) {
    int i = blockIdx.x * blockDim.x + threadIdx.x;
    const int T1 = D_H * KPAD1;
    if (i < T1) {
        int n = i / KPAD1, k = i % KPAD1;
        g_W1T[i] = (k < D_INPUT) ? to_tf32(W1[(size_t)k * D_H + n]) : 0.f;
    } else {
        int j = i - T1;
        if (j < D_H * D_H) {
            int n = j / D_H, k = j % D_H;
            g_W2T[j] = to_tf32(W2[(size_t)k * D_H + n]);
        }
    }
}

// ---------------- GEMM core ----------------
// 512 threads = 16 warps: wm = wid&3 (M), wn = wid>>2 (N). CTA tile 128x192,
// warp tile 32x48. Register-pipelined double-buffered smem, pitch-36 staging.
// smem: As 2x[128][36], Bs 2x[192][36]  -> 92160 bytes dynamic.
#define A_STAGE (128 * P36)
#define B_STAGE (192 * P36)
#define GEMM_SMEM ((2 * A_STAGE + 2 * B_STAGE) * 4)

struct Frag { float c[2][6][4]; };

__device__ __forceinline__ void gemm_compute(const float* __restrict__ A,
                                             const float* __restrict__ B,
                                             Frag& f, int wm, int wn, int gid, int tig)
{
    #pragma unroll
    for (int ks = 0; ks < 4; ks++) {
        const int kk = ks * 8;
        float a[2][4];
        #pragma unroll
        for (int mt = 0; mt < 2; mt++) {
            const int r = wm * 32 + mt * 16 + gid;
            a[mt][0] = A[r * P36 + kk + tig];
            a[mt][1] = A[(r + 8) * P36 + kk + tig];
            a[mt][2] = A[r * P36 + kk + tig + 4];
            a[mt][3] = A[(r + 8) * P36 + kk + tig + 4];
        }
        float b[6][2];
        #pragma unroll
        for (int nt = 0; nt < 6; nt++) {
            const int n = wn * 48 + nt * 8 + gid;
            b[nt][0] = B[n * P36 + kk + tig];
            b[nt][1] = B[n * P36 + kk + tig + 4];
        }
        #pragma unroll
        for (int mt = 0; mt < 2; mt++)
            #pragma unroll
            for (int nt = 0; nt < 6; nt++)
                mma8(f.c[mt][nt], a[mt], b[nt]);
    }
}

// ---------- stage 1: h = tf32(relu(x @ W1 + b1)) ----------
__global__ void __launch_bounds__(512) gemm1_kernel(
    const float* __restrict__ x, const float* __restrict__ b1)
{
    extern __shared__ float sm[];
    float* As = sm;
    float* Bs = sm + 2 * A_STAGE;

    const int tid  = threadIdx.x;
    const int lane = tid & 31;
    const int wid  = tid >> 5;
    const int wm   = wid & 3, wn = wid >> 2;
    const int gid  = lane >> 2, tig = lane & 3;
    const int row0 = blockIdx.x * 128;

    const int lr = tid >> 5;          // A-load row base helper? (i>>5 done per t)
    (void)lr;

    Frag f;
    #pragma unroll
    for (int mt = 0; mt < 2; mt++)
        #pragma unroll
        for (int nt = 0; nt < 6; nt++)
            #pragma unroll
            for (int q = 0; q < 4; q++) f.c[mt][nt][q] = 0.f;

    float xa[8], wb[12];

    // ---- load chunk 0 ----
    #pragma unroll
    for (int t = 0; t < 8; t++) {
        int i = tid + t * 512, r = i >> 5, k = i & 31;
        xa[t] = (k < D_INPUT) ? __ldg(&x[(size_t)(row0 + r) * D_INPUT + k]) : 0.f;
    }
    #pragma unroll
    for (int t = 0; t < 12; t++) {
        int i = tid + t * 512, n = i >> 5, k = i & 31;
        wb[t] = __ldg(&g_W1T[n * KPAD1 + k]);
    }
    #pragma unroll
    for (int t = 0; t < 8; t++) {
        int i = tid + t * 512, r = i >> 5, k = i & 31;
        As[r * P36 + k] = to_tf32(xa[t]);
    }
    #pragma unroll
    for (int t = 0; t < 12; t++) {
        int i = tid + t * 512, n = i >> 5, k = i & 31;
        Bs[n * P36 + k] = wb[t];
    }
    __syncthreads();

    for (int c = 0; c < NCH1; c++) {
        const int nxt = c + 1;
        if (nxt < NCH1) {                       // issue loads for next chunk
            #pragma unroll
            for (int t = 0; t < 8; t++) {
                int i = tid + t * 512, r = i >> 5, k = nxt * 32 + (i & 31);
                xa[t] = (k < D_INPUT) ? __ldg(&x[(size_t)(row0 + r) * D_INPUT + k]) : 0.f;
            }
            #pragma unroll
            for (int t = 0; t < 12; t++) {
                int i = tid + t * 512, n = i >> 5, k = i & 31;
                wb[t] = __ldg(&g_W1T[n * KPAD1 + nxt * 32 + k]);
            }
        }
        gemm_compute(As + (c & 1) * A_STAGE, Bs + (c & 1) * B_STAGE, f, wm, wn, gid, tig);
        __syncthreads();
        if (nxt < NCH1) {
            float* Ad = As + (nxt & 1) * A_STAGE;
            float* Bd = Bs + (nxt & 1) * B_STAGE;
            #pragma unroll
            for (int t = 0; t < 8; t++) {
                int i = tid + t * 512, r = i >> 5, k = i & 31;
                Ad[r * P36 + k] = to_tf32(xa[t]);
            }
            #pragma unroll
            for (int t = 0; t < 12; t++) {
                int i = tid + t * 512, n = i >> 5, k = i & 31;
                Bd[n * P36 + k] = wb[t];
            }
            __syncthreads();
        }
    }

    // ---- epilogue: h = tf32(relu(c + b1)) ----
    #pragma unroll
    for (int mt = 0; mt < 2; mt++) {
        const int r = row0 + wm * 32 + mt * 16 + gid;
        #pragma unroll
        for (int nt = 0; nt < 6; nt++) {
            const int n = wn * 48 + nt * 8 + 2 * tig;
            const float bb0 = __ldg(&b1[n]), bb1 = __ldg(&b1[n + 1]);
            float2 v0, v1;
            v0.x = to_tf32(fmaxf(f.c[mt][nt][0] + bb0, 0.f));
            v0.y = to_tf32(fmaxf(f.c[mt][nt][1] + bb1, 0.f));
            v1.x = to_tf32(fmaxf(f.c[mt][nt][2] + bb0, 0.f));
            v1.y = to_tf32(fmaxf(f.c[mt][nt][3] + bb1, 0.f));
            *(float2*)&g_h[(size_t)r * D_H + n]       = v0;
            *(float2*)&g_h[(size_t)(r + 8) * D_H + n] = v1;
        }
    }
}

// ---------- stage 2: feat = relu(h @ W2 + b2) ----------
__global__ void __launch_bounds__(512) gemm2_kernel(const float* __restrict__ b2)
{
    extern __shared__ float sm[];
    float* As = sm;
    float* Bs = sm + 2 * A_STAGE;

    const int tid  = threadIdx.x;
    const int lane = tid & 31;
    const int wid  = tid >> 5;
    const int wm   = wid & 3, wn = wid >> 2;
    const int gid  = lane >> 2, tig = lane & 3;
    const int row0 = blockIdx.x * 128;

    Frag f;
    #pragma unroll
    for (int mt = 0; mt < 2; mt++)
        #pragma unroll
        for (int nt = 0; nt < 6; nt++)
            #pragma unroll
            for (int q = 0; q < 4; q++) f.c[mt][nt][q] = 0.f;

    float xa[8], wb[12];

    #pragma unroll
    for (int t = 0; t < 8; t++) {
        int i = tid + t * 512, r = i >> 5, k = i & 31;
        xa[t] = g_h[(size_t)(row0 + r) * D_H + k];
    }
    #pragma unroll
    for (int t = 0; t < 12; t++) {
        int i = tid + t * 512, n = i >> 5, k = i & 31;
        wb[t] = __ldg(&g_W2T[n * D_H + k]);
    }
    #pragma unroll
    for (int t = 0; t < 8; t++) {
        int i = tid + t * 512, r = i >> 5, k = i & 31;
        As[r * P36 + k] = xa[t];
    }
    #pragma unroll
    for (int t = 0; t < 12; t++) {
        int i = tid + t * 512, n = i >> 5, k = i & 31;
        Bs[n * P36 + k] = wb[t];
    }
    __syncthreads();

    for (int c = 0; c < NCH2; c++) {
        const int nxt = c + 1;
        if (nxt < NCH2) {
            #pragma unroll
            for (int t = 0; t < 8; t++) {
                int i = tid + t * 512, r = i >> 5, k = nxt * 32 + (i & 31);
                xa[t] = g_h[(size_t)(row0 + r) * D_H + k];
            }
            #pragma unroll
            for (int t = 0; t < 12; t++) {
                int i = tid + t * 512, n = i >> 5, k = i & 31;
                wb[t] = __ldg(&g_W2T[n * D_H + nxt * 32 + k]);
            }
        }
        gemm_compute(As + (c & 1) * A_STAGE, Bs + (c & 1) * B_STAGE, f, wm, wn, gid, tig);
        __syncthreads();
        if (nxt < NCH2) {
            float* Ad = As + (nxt & 1) * A_STAGE;
            float* Bd = Bs + (nxt & 1) * B_STAGE;
            #pragma unroll
            for (int t = 0; t < 8; t++) {
                int i = tid + t * 512, r = i >> 5, k = i & 31;
                Ad[r * P36 + k] = xa[t];
            }
            #pragma unroll
            for (int t = 0; t < 12; t++) {
                int i = tid + t * 512, n = i >> 5, k = i & 31;
                Bd[n * P36 + k] = wb[t];
            }
            __syncthreads();
        }
    }

    // ---- epilogue: feat = relu(c + b2), full fp32 ----
    #pragma unroll
    for (int mt = 0; mt < 2; mt++) {
        const int r = row0 + wm * 32 + mt * 16 + gid;
        #pragma unroll
        for (int nt = 0; nt < 6; nt++) {
            const int n = wn * 48 + nt * 8 + 2 * tig;
            const float bb0 = __ldg(&b2[n]), bb1 = __ldg(&b2[n + 1]);
            float2 v0, v1;
            v0.x = fmaxf(f.c[mt][nt][0] + bb0, 0.f);
            v0.y = fmaxf(f.c[mt][nt][1] + bb1, 0.f);
            v1.x = fmaxf(f.c[mt][nt][2] + bb0, 0.f);
            v1.y = fmaxf(f.c[mt][nt][3] + bb1, 0.f);
            *(float2*)&g_feat[(size_t)r * D_H + n]       = v0;
            *(float2*)&g_feat[(size_t)(r + 8) * D_H + n] = v1;
        }
    }
}

// ---------------- binning: histogram -> scan -> scatter ----------------
__global__ void zero_kernel() {
    int i = blockIdx.x * blockDim.x + threadIdx.x;
    if (i < NHEADS) g_cnt[i] = 0;
}

__global__ void hist_kernel(const int* __restrict__ qid, const int* __restrict__ cor) {
    int b = blockIdx.x * blockDim.x + threadIdx.x;
    if (b < B_TOTAL) atomicAdd(&g_cnt[qid[b] + cor[b] * NQ], 1);
}

__global__ void scan_kernel() {   // single block of 1024, Hillis-Steele over 2048
    __shared__ int s[2048];
    const int t = threadIdx.x;
    s[t]        = (t < NHEADS) ? g_cnt[t] : 0;
    s[t + 1024] = (t + 1024 < NHEADS) ? g_cnt[t + 1024] : 0;
    __syncthreads();
    for (int d = 1; d < 2048; d <<= 1) {
        int v0 = s[t], v1 = s[t + 1024];
        int a0 = (t >= d) ? s[t - d] : 0;
        int a1 = (t + 1024 >= d) ? s[t + 1024 - d] : 0;
        __syncthreads();
        s[t] = v0 + a0;
        s[t + 1024] = v1 + a1;
        __syncthreads();
    }
    if (t < NHEADS)          { int e = (t == 0) ? 0 : s[t - 1]; g_off[t] = e; g_cur[t] = e; }
    if (t + 1024 < NHEADS)   { int e = s[t + 1023];             g_off[t + 1024] = e; g_cur[t + 1024] = e; }
    if (t == 0) g_off[NHEADS] = s[NHEADS - 1];
}

__global__ void scatter_kernel(const int* __restrict__ qid, const int* __restrict__ cor) {
    int b = blockIdx.x * blockDim.x + threadIdx.x;
    if (b < B_TOTAL) {
        int h = qid[b] + cor[b] * NQ;
        int p = atomicAdd(&g_cur[h], 1);
        g_order[p] = b;
    }
}

// ---------------- routed heads: one CTA per head group ----------------
__global__ void __launch_bounds__(256) heads_kernel(
    const float* __restrict__ Wh, const float* __restrict__ bh, float* __restrict__ out)
{
    const int g = blockIdx.x;
    const int t = threadIdx.x;
    const int c = t & 15, j = t >> 4;

    __shared__ float s_feat[D_H];
    __shared__ float s_part[256];
    __shared__ float s_bq[NC];

    float w[12];
    const float* wp = Wh + ((size_t)g * NC + c) * D_H + j * 12;
    #pragma unroll
    for (int u = 0; u < 12; u++) w[u] = wp[u];
    if (t < NC) s_bq[t] = bh[g * NC + t];

    const int start = g_off[g], end = g_off[g + 1];

    float nxt = 0.f;
    if (start < end && t < D_H) nxt = g_feat[(size_t)g_order[start] * D_H + t];
    __syncthreads();

    for (int s = start; s < end; s++) {
        if (t < D_H) s_feat[t] = nxt;
        __syncthreads();
        if (s + 1 < end && t < D_H)
            nxt = g_feat[(size_t)g_order[s + 1] * D_H + t];
        float p = 0.f;
        const float* f = s_feat + j * 12;
        #pragma unroll
        for (int u = 0; u < 12; u++) p += w[u] * f[u];
        s_part[t] = p;
        __syncthreads();
        if (t < NC) {
            float sum = s_bq[t];
            #pragma unroll
            for (int jj = 0; jj < 16; jj++) sum += s_part[t + 16 * jj];
            out[(size_t)g_order[s] * NC + t] = sum;
        }
        __syncthreads();
    }
}

// ---------------- launch ----------------
extern "C" void kernel_launch(void* const* d_in, const int* in_sizes, int n_in,
                              void* d_out, int out_size) {
    const float* x   = (const float*)d_in[0];
    const int*   qid = (const int*)d_in[1];
    const int*   cor = (const int*)d_in[2];
    const float* W1  = (const float*)d_in[3];
    const float* b1  = (const float*)d_in[4];
    const float* W2  = (const float*)d_in[5];
    const float* b2  = (const float*)d_in[6];
    const float* Wh  = (const float*)d_in[7];
    const float* bh  = (const float*)d_in[8];
    float* out = (float*)d_out;

    cudaFuncSetAttribute(gemm1_kernel, cudaFuncAttributeMaxDynamicSharedMemorySize, GEMM_SMEM);
    cudaFuncSetAttribute(gemm2_kernel, cudaFuncAttributeMaxDynamicSharedMemorySize, GEMM_SMEM);

    // binning first (independent of trunk) so ncu's -s 5 window lands on gemm1
    zero_kernel<<<(NHEADS + 255) / 256, 256>>>();
    hist_kernel<<<(B_TOTAL + 255) / 256, 256>>>(qid, cor);
    scan_kernel<<<1, 1024>>>();
    scatter_kernel<<<(B_TOTAL + 255) / 256, 256>>>(qid, cor);
    prep_kernel<<<(D_H * KPAD1 + D_H * D_H + 255) / 256, 256>>>(W1, W2);
    gemm1_kernel<<<B_TOTAL / 128, 512, GEMM_SMEM>>>(x, b1);
    gemm2_kernel<<<B_TOTAL / 128, 512, GEMM_SMEM>>>(b2);
    heads_kernel<<<NHEADS, 256>>>(Wh, bh, out);
}

// round 4
// speedup vs baseline: 1.8468x; 1.2187x over previous
#include <cuda_runtime.h>
#include <cuda_fp16.h>
#include <cstdint>
#include <cstddef>

// ---------------- problem constants ----------------
#define B_TOTAL 131072
#define D_INPUT 385
#define D_H     192
#define NQ      1000
#define NHEADS  2000
#define NC      16

#define KPAD1   416            // 13 chunks of 32
#define NCH1    13
#define NCH2    6
#define PW      40             // smem pitch in 32-bit words (8 mod 32 -> conflict-free LDS.64)

// ---------------- scratch (device globals: allocation-free) ----------------
__device__ uint32_t g_h[(size_t)B_TOTAL * (D_H / 2)];     // hidden, fp16 permuted, 50 MB
__device__ float    g_feat[(size_t)B_TOTAL * D_H];        // trunk output fp32, 100 MB
__device__ uint32_t g_W1Tw[D_H * (KPAD1 / 2)];            // W1^T fp16, permuted, padded
__device__ uint32_t g_W2Tw[D_H * (D_H / 2)];              // W2^T fp16, permuted
__device__ int      g_cnt[NHEADS];
__device__ int      g_off[NHEADS + 1];
__device__ int      g_cur[NHEADS];
__device__ int      g_order[B_TOTAL];

// ---------------- helpers ----------------
// permuted position of half kk (0..31) within a 32-half k-chunk:
// logical word w in 8-group -> phys [0,4,1,5,2,6,3,7] so frag pairs (tig, tig+4)
// land in adjacent words -> LDS.64 fragments.
__device__ __forceinline__ int phys_half(int kk) {
    int lw = kk >> 1, w = lw & 7, g = lw >> 3;
    int pw = g * 8 + ((w & 4) ? ((w & 3) * 2 + 1) : (w * 2));
    return pw * 2 + (kk & 1);
}

__device__ __forceinline__ void mma16(float c[4], uint32_t a0, uint32_t a1,
                                      uint32_t a2, uint32_t a3, uint32_t b0, uint32_t b1) {
    asm volatile(
        "mma.sync.aligned.m16n8k16.row.col.f32.f16.f16.f32 "
        "{%0,%1,%2,%3}, {%4,%5,%6,%7}, {%8,%9}, {%0,%1,%2,%3};\n"
        : "+f"(c[0]), "+f"(c[1]), "+f"(c[2]), "+f"(c[3])
        : "r"(a0), "r"(a1), "r"(a2), "r"(a3), "r"(b0), "r"(b1));
}

// ---------------- prep: W1/W2 -> transposed fp16, chunk-permuted ----------------
__global__ void prep_kernel(const float* __restrict__ W1, const float* __restrict__ W2) {
    int i = blockIdx.x * blockDim.x + threadIdx.x;
    const int T1 = D_H * KPAD1;
    __half* W1h = (__half*)g_W1Tw;
    __half* W2h = (__half*)g_W2Tw;
    if (i < T1) {
        int n = i / KPAD1, k = i % KPAD1;
        float v = (k < D_INPUT) ? W1[(size_t)k * D_H + n] : 0.f;
        W1h[n * KPAD1 + (k >> 5) * 32 + phys_half(k & 31)] = __float2half_rn(v);
    } else {
        int j = i - T1;
        if (j < D_H * D_H) {
            int n = j / D_H, k = j % D_H;
            W2h[n * D_H + (k >> 5) * 32 + phys_half(k & 31)] = __float2half_rn(W2[(size_t)k * D_H + n]);
        }
    }
}

// ---------------- GEMM core (fp16 m16n8k16) ----------------
// 512 threads = 16 warps: wm = wid&3 (M, 32 rows), wn = wid>>2 (N, 48 cols).
// CTA tile 128x192. smem: A 2x[128][PW words], B 2x[192][PW words].
#define A_STAGE (128 * PW)     // words
#define B_STAGE (192 * PW)
#define GEMM_SMEM ((2 * A_STAGE + 2 * B_STAGE) * 4)

struct Frag { float c[2][6][4]; };

__device__ __forceinline__ void gemm_compute16(const uint32_t* __restrict__ A,
                                               const uint32_t* __restrict__ B,
                                               Frag& f, int wm, int wn, int gid, int tig)
{
    #pragma unroll
    for (int g = 0; g < 2; g++) {          // two k16 steps per 32-k chunk
        uint2 av[2][2];
        #pragma unroll
        for (int mt = 0; mt < 2; mt++) {
            const int r = wm * 32 + mt * 16 + gid;
            av[mt][0] = *(const uint2*)(A + r * PW + g * 8 + 2 * tig);
            av[mt][1] = *(const uint2*)(A + (r + 8) * PW + g * 8 + 2 * tig);
        }
        uint2 bv[6];
        #pragma unroll
        for (int nt = 0; nt < 6; nt++) {
            const int n = wn * 48 + nt * 8 + gid;
            bv[nt] = *(const uint2*)(B + n * PW + g * 8 + 2 * tig);
        }
        #pragma unroll
        for (int mt = 0; mt < 2; mt++)
            #pragma unroll
            for (int nt = 0; nt < 6; nt++)
                mma16(f.c[mt][nt], av[mt][0].x, av[mt][1].x, av[mt][0].y, av[mt][1].y,
                      bv[nt].x, bv[nt].y);
    }
}

// ---------- stage 1: h = fp16(relu(x @ W1 + b1)) ----------
__global__ void __launch_bounds__(512) gemm1_kernel(
    const float* __restrict__ x, const float* __restrict__ b1)
{
    extern __shared__ uint32_t sm[];
    uint32_t* As = sm;
    uint32_t* Bs = sm + 2 * A_STAGE;

    const int tid  = threadIdx.x;
    const int lane = tid & 31;
    const int wid  = tid >> 5;
    const int wm   = wid & 3, wn = wid >> 2;
    const int gid  = lane >> 2, tig = lane & 3;
    const int row0 = blockIdx.x * 128;

    const int myk  = tid & 31;             // fixed k for A loads
    const int ph   = phys_half(myk);       // fixed phys half position

    Frag f;
    #pragma unroll
    for (int mt = 0; mt < 2; mt++)
        #pragma unroll
        for (int nt = 0; nt < 6; nt++)
            #pragma unroll
            for (int q = 0; q < 4; q++) f.c[mt][nt][q] = 0.f;

    float xa[8]; uint32_t wb[6];

    // ---- load + stage chunk 0 ----
    {
        const bool kv = (myk < D_INPUT);
        #pragma unroll
        for (int t = 0; t < 8; t++) {
            int r = (tid + t * 512) >> 5;
            xa[t] = kv ? __ldg(&x[(size_t)(row0 + r) * D_INPUT + myk]) : 0.f;
        }
        #pragma unroll
        for (int t = 0; t < 6; t++) {
            int i = tid + t * 512, n = i >> 4, w = i & 15;
            wb[t] = __ldg(&g_W1Tw[n * (KPAD1 / 2) + w]);
        }
        __half* Ah = (__half*)As;
        #pragma unroll
        for (int t = 0; t < 8; t++) {
            int r = (tid + t * 512) >> 5;
            Ah[r * (PW * 2) + ph] = __float2half_rn(xa[t]);
        }
        #pragma unroll
        for (int t = 0; t < 6; t++) {
            int i = tid + t * 512, n = i >> 4, w = i & 15;
            Bs[n * PW + w] = wb[t];
        }
    }
    __syncthreads();

    for (int c = 0; c < NCH1; c++) {
        const int nxt = c + 1;
        if (nxt < NCH1) {
            const int k = nxt * 32 + myk;
            const bool kv = (k < D_INPUT);
            #pragma unroll
            for (int t = 0; t < 8; t++) {
                int r = (tid + t * 512) >> 5;
                xa[t] = kv ? __ldg(&x[(size_t)(row0 + r) * D_INPUT + k]) : 0.f;
            }
            #pragma unroll
            for (int t = 0; t < 6; t++) {
                int i = tid + t * 512, n = i >> 4, w = i & 15;
                wb[t] = __ldg(&g_W1Tw[n * (KPAD1 / 2) + nxt * 16 + w]);
            }
        }
        gemm_compute16(As + (c & 1) * A_STAGE, Bs + (c & 1) * B_STAGE, f, wm, wn, gid, tig);
        __syncthreads();
        if (nxt < NCH1) {
            __half* Ah = (__half*)(As + (nxt & 1) * A_STAGE);
            uint32_t* Bd = Bs + (nxt & 1) * B_STAGE;
            #pragma unroll
            for (int t = 0; t < 8; t++) {
                int r = (tid + t * 512) >> 5;
                Ah[r * (PW * 2) + ph] = __float2half_rn(xa[t]);
            }
            #pragma unroll
            for (int t = 0; t < 6; t++) {
                int i = tid + t * 512, n = i >> 4, w = i & 15;
                Bd[n * PW + w] = wb[t];
            }
            __syncthreads();
        }
    }

    // ---- epilogue: g_h = fp16(relu(c + b1)), pre-permuted for gemm2 ----
    #pragma unroll
    for (int mt = 0; mt < 2; mt++) {
        const int r = row0 + wm * 32 + mt * 16 + gid;
        #pragma unroll
        for (int nt = 0; nt < 6; nt++) {
            const int n = wn * 48 + nt * 8 + 2 * tig;
            const float bb0 = __ldg(&b1[n]), bb1 = __ldg(&b1[n + 1]);
            // word position: chunk (n>>5)*16 + phys word of (n&31)
            const int lw = (n & 31) >> 1, w = lw & 7, g2 = lw >> 3;
            const int pw = (n >> 5) * 16 + g2 * 8 + ((w & 4) ? ((w & 3) * 2 + 1) : (w * 2));
            __half2 v0 = __floats2half2_rn(fmaxf(f.c[mt][nt][0] + bb0, 0.f),
                                           fmaxf(f.c[mt][nt][1] + bb1, 0.f));
            __half2 v1 = __floats2half2_rn(fmaxf(f.c[mt][nt][2] + bb0, 0.f),
                                           fmaxf(f.c[mt][nt][3] + bb1, 0.f));
            g_h[(size_t)r * 96 + pw]       = *(uint32_t*)&v0;
            g_h[(size_t)(r + 8) * 96 + pw] = *(uint32_t*)&v1;
        }
    }
}

// ---------- stage 2: feat = relu(h @ W2 + b2) ----------
__global__ void __launch_bounds__(512) gemm2_kernel(const float* __restrict__ b2)
{
    extern __shared__ uint32_t sm[];
    uint32_t* As = sm;
    uint32_t* Bs = sm + 2 * A_STAGE;

    const int tid  = threadIdx.x;
    const int lane = tid & 31;
    const int wid  = tid >> 5;
    const int wm   = wid & 3, wn = wid >> 2;
    const int gid  = lane >> 2, tig = lane & 3;
    const int row0 = blockIdx.x * 128;

    Frag f;
    #pragma unroll
    for (int mt = 0; mt < 2; mt++)
        #pragma unroll
        for (int nt = 0; nt < 6; nt++)
            #pragma unroll
            for (int q = 0; q < 4; q++) f.c[mt][nt][q] = 0.f;

    uint32_t xa[4], wb[6];

    #pragma unroll
    for (int t = 0; t < 4; t++) {
        int i = tid + t * 512, r = i >> 4, w = i & 15;
        xa[t] = g_h[(size_t)(row0 + r) * 96 + w];
    }
    #pragma unroll
    for (int t = 0; t < 6; t++) {
        int i = tid + t * 512, n = i >> 4, w = i & 15;
        wb[t] = __ldg(&g_W2Tw[n * 96 + w]);
    }
    #pragma unroll
    for (int t = 0; t < 4; t++) {
        int i = tid + t * 512, r = i >> 4, w = i & 15;
        As[r * PW + w] = xa[t];
    }
    #pragma unroll
    for (int t = 0; t < 6; t++) {
        int i = tid + t * 512, n = i >> 4, w = i & 15;
        Bs[n * PW + w] = wb[t];
    }
    __syncthreads();

    for (int c = 0; c < NCH2; c++) {
        const int nxt = c + 1;
        if (nxt < NCH2) {
            #pragma unroll
            for (int t = 0; t < 4; t++) {
                int i = tid + t * 512, r = i >> 4, w = i & 15;
                xa[t] = g_h[(size_t)(row0 + r) * 96 + nxt * 16 + w];
            }
            #pragma unroll
            for (int t = 0; t < 6; t++) {
                int i = tid + t * 512, n = i >> 4, w = i & 15;
                wb[t] = __ldg(&g_W2Tw[n * 96 + nxt * 16 + w]);
            }
        }
        gemm_compute16(As + (c & 1) * A_STAGE, Bs + (c & 1) * B_STAGE, f, wm, wn, gid, tig);
        __syncthreads();
        if (nxt < NCH2) {
            uint32_t* Ad = As + (nxt & 1) * A_STAGE;
            uint32_t* Bd = Bs + (nxt & 1) * B_STAGE;
            #pragma unroll
            for (int t = 0; t < 4; t++) {
                int i = tid + t * 512, r = i >> 4, w = i & 15;
                Ad[r * PW + w] = xa[t];
            }
            #pragma unroll
            for (int t = 0; t < 6; t++) {
                int i = tid + t * 512, n = i >> 4, w = i & 15;
                Bd[n * PW + w] = wb[t];
            }
            __syncthreads();
        }
    }

    // ---- epilogue: feat = relu(c + b2), full fp32 ----
    #pragma unroll
    for (int mt = 0; mt < 2; mt++) {
        const int r = row0 + wm * 32 + mt * 16 + gid;
        #pragma unroll
        for (int nt = 0; nt < 6; nt++) {
            const int n = wn * 48 + nt * 8 + 2 * tig;
            const float bb0 = __ldg(&b2[n]), bb1 = __ldg(&b2[n + 1]);
            float2 v0, v1;
            v0.x = fmaxf(f.c[mt][nt][0] + bb0, 0.f);
            v0.y = fmaxf(f.c[mt][nt][1] + bb1, 0.f);
            v1.x = fmaxf(f.c[mt][nt][2] + bb0, 0.f);
            v1.y = fmaxf(f.c[mt][nt][3] + bb1, 0.f);
            *(float2*)&g_feat[(size_t)r * D_H + n]       = v0;
            *(float2*)&g_feat[(size_t)(r + 8) * D_H + n] = v1;
        }
    }
}

// ---------------- binning: histogram -> scan -> scatter ----------------
__global__ void zero_kernel() {
    int i = blockIdx.x * blockDim.x + threadIdx.x;
    if (i < NHEADS) g_cnt[i] = 0;
}

__global__ void hist_kernel(const int* __restrict__ qid, const int* __restrict__ cor) {
    int b = blockIdx.x * blockDim.x + threadIdx.x;
    if (b < B_TOTAL) atomicAdd(&g_cnt[qid[b] + cor[b] * NQ], 1);
}

__global__ void scan_kernel() {   // single block of 1024, Hillis-Steele over 2048
    __shared__ int s[2048];
    const int t = threadIdx.x;
    s[t]        = (t < NHEADS) ? g_cnt[t] : 0;
    s[t + 1024] = (t + 1024 < NHEADS) ? g_cnt[t + 1024] : 0;
    __syncthreads();
    for (int d = 1; d < 2048; d <<= 1) {
        int v0 = s[t], v1 = s[t + 1024];
        int a0 = (t >= d) ? s[t - d] : 0;
        int a1 = (t + 1024 >= d) ? s[t + 1024 - d] : 0;
        __syncthreads();
        s[t] = v0 + a0;
        s[t + 1024] = v1 + a1;
        __syncthreads();
    }
    if (t < NHEADS)          { int e = (t == 0) ? 0 : s[t - 1]; g_off[t] = e; g_cur[t] = e; }
    if (t + 1024 < NHEADS)   { int e = s[t + 1023];             g_off[t + 1024] = e; g_cur[t + 1024] = e; }
    if (t == 0) g_off[NHEADS] = s[NHEADS - 1];
}

__global__ void scatter_kernel(const int* __restrict__ qid, const int* __restrict__ cor) {
    int b = blockIdx.x * blockDim.x + threadIdx.x;
    if (b < B_TOTAL) {
        int h = qid[b] + cor[b] * NQ;
        int p = atomicAdd(&g_cur[h], 1);
        g_order[p] = b;
    }
}

// ---------------- routed heads: one CTA per head group ----------------
__global__ void __launch_bounds__(256) heads_kernel(
    const float* __restrict__ Wh, const float* __restrict__ bh, float* __restrict__ out)
{
    const int g = blockIdx.x;
    const int t = threadIdx.x;
    const int c = t & 15, j = t >> 4;

    __shared__ float s_feat[D_H];
    __shared__ float s_part[256];
    __shared__ float s_bq[NC];

    float w[12];
    const float* wp = Wh + ((size_t)g * NC + c) * D_H + j * 12;
    #pragma unroll
    for (int u = 0; u < 12; u++) w[u] = wp[u];
    if (t < NC) s_bq[t] = bh[g * NC + t];

    const int start = g_off[g], end = g_off[g + 1];

    float nxt = 0.f;
    if (start < end && t < D_H) nxt = g_feat[(size_t)g_order[start] * D_H + t];
    __syncthreads();

    for (int s = start; s < end; s++) {
        if (t < D_H) s_feat[t] = nxt;
        __syncthreads();
        if (s + 1 < end && t < D_H)
            nxt = g_feat[(size_t)g_order[s + 1] * D_H + t];
        float p = 0.f;
        const float* f = s_feat + j * 12;
        #pragma unroll
        for (int u = 0; u < 12; u++) p += w[u] * f[u];
        s_part[t] = p;
        __syncthreads();
        if (t < NC) {
            float sum = s_bq[t];
            #pragma unroll
            for (int jj = 0; jj < 16; jj++) sum += s_part[t + 16 * jj];
            out[(size_t)g_order[s] * NC + t] = sum;
        }
        __syncthreads();
    }
}

// ---------------- launch ----------------
extern "C" void kernel_launch(void* const* d_in, const int* in_sizes, int n_in,
                              void* d_out, int out_size) {
    const float* x   = (const float*)d_in[0];
    const int*   qid = (const int*)d_in[1];
    const int*   cor = (const int*)d_in[2];
    const float* W1  = (const float*)d_in[3];
    const float* b1  = (const float*)d_in[4];
    const float* W2  = (const float*)d_in[5];
    const float* b2  = (const float*)d_in[6];
    const float* Wh  = (const float*)d_in[7];
    const float* bh  = (const float*)d_in[8];
    float* out = (float*)d_out;

    cudaFuncSetAttribute(gemm1_kernel, cudaFuncAttributeMaxDynamicSharedMemorySize, GEMM_SMEM);
    cudaFuncSetAttribute(gemm2_kernel, cudaFuncAttributeMaxDynamicSharedMemorySize, GEMM_SMEM);

    // order chosen so gemm1 is the 4th launch (profiler window)
    zero_kernel<<<(NHEADS + 255) / 256, 256>>>();
    hist_kernel<<<(B_TOTAL + 255) / 256, 256>>>(qid, cor);
    prep_kernel<<<(D_H * KPAD1 + D_H * D_H + 255) / 256, 256>>>(W1, W2);
    gemm1_kernel<<<B_TOTAL / 128, 512, GEMM_SMEM>>>(x, b1);
    gemm2_kernel<<<B_TOTAL / 128, 512, GEMM_SMEM>>>(b2);
    scan_kernel<<<1, 1024>>>();
    scatter_kernel<<<(B_TOTAL + 255) / 256, 256>>>(qid, cor);
    heads_kernel<<<NHEADS, 256>>>(Wh, bh, out);
}

// round 5
// speedup vs baseline: 1.8839x; 1.0201x over previous
#include <cuda_runtime.h>
#include <cuda_fp16.h>
#include <cstdint>
#include <cstddef>

// ---------------- problem constants ----------------
#define B_TOTAL 131072
#define D_INPUT 385
#define D_H     192
#define NQ      1000
#define NHEADS  2000
#define NC      16

#define KPAD1   416            // 13 chunks of 32
#define NCH1    13
#define NCH2    6
#define PA      40             // A smem pitch (halves); 80B row stride -> LDSM conflict-free
#define PB      40             // B smem pitch (halves), gemm1
#define PW2     200            // W2 smem pitch (halves), gemm2; 400B stride -> conflict-free

// ---------------- scratch (device globals: allocation-free) ----------------
__device__ uint32_t g_h[(size_t)B_TOTAL * 96];     // hidden fp16, plain [r][192], 50 MB
__device__ float    g_feat[(size_t)B_TOTAL * D_H]; // trunk output fp32, 100 MB
__device__ __half   g_W1h[D_H * KPAD1];            // W1^T fp16 [n][KPAD1], zero-padded
__device__ __half   g_W2h[D_H * D_H];              // W2^T fp16 [n][192]
__device__ int      g_cnt[NHEADS];
__device__ int      g_off[NHEADS + 1];
__device__ int      g_cur[NHEADS];
__device__ int      g_order[B_TOTAL];

// ---------------- PTX helpers ----------------
#define CP16(dst, src) \
    asm volatile("cp.async.cg.shared.global [%0], [%1], 16;" \
                 :: "r"(dst), "l"(__cvta_generic_to_global((const void*)(src))))
#define CP_COMMIT() asm volatile("cp.async.commit_group;" ::: "memory")
#define CP_WAIT0()  asm volatile("cp.async.wait_group 0;" ::: "memory")

__device__ __forceinline__ void ldsm4(uint32_t r[4], uint32_t addr) {
    asm volatile("ldmatrix.sync.aligned.m8n8.x4.shared.b16 {%0,%1,%2,%3}, [%4];"
        : "=r"(r[0]), "=r"(r[1]), "=r"(r[2]), "=r"(r[3]) : "r"(addr));
}

__device__ __forceinline__ void mma16(float c[4], uint32_t a0, uint32_t a1,
                                      uint32_t a2, uint32_t a3, uint32_t b0, uint32_t b1) {
    asm volatile(
        "mma.sync.aligned.m16n8k16.row.col.f32.f16.f16.f32 "
        "{%0,%1,%2,%3}, {%4,%5,%6,%7}, {%8,%9}, {%0,%1,%2,%3};\n"
        : "+f"(c[0]), "+f"(c[1]), "+f"(c[2]), "+f"(c[3])
        : "r"(a0), "r"(a1), "r"(a2), "r"(a3), "r"(b0), "r"(b1));
}

// ---------------- prep: W1/W2 -> transposed fp16 (plain layout) ----------------
__global__ void prep_kernel(const float* __restrict__ W1, const float* __restrict__ W2) {
    int i = blockIdx.x * blockDim.x + threadIdx.x;
    const int T1 = D_H * KPAD1;
    if (i < T1) {
        int n = i / KPAD1, k = i - n * KPAD1;
        float v = (k < D_INPUT) ? W1[(size_t)k * D_H + n] : 0.f;
        g_W1h[i] = __float2half_rn(v);
    } else {
        int j = i - T1;
        if (j < D_H * D_H) {
            int n = j / D_H, k = j - n * D_H;
            g_W2h[j] = __float2half_rn(W2[(size_t)k * D_H + n]);
        }
    }
}

// ---------------- GEMM core ----------------
// 512 threads = 16 warps: wm = wid&3 (M, 32 rows), wn = wid>>2 (N, 48 cols).
// CTA tile 128x192. Fragments via ldmatrix.x4, fp16 m16n8k16.
struct Frag { float c[2][6][4]; };

template<int PBH>
__device__ __forceinline__ void compute_chunk(uint32_t abase, uint32_t bbase,
                                              Frag& f, int wm, int wn, int lane)
{
    const int arow = ((lane >> 3) & 1) * 8 + (lane & 7);
    const int ak   = (lane >> 4) * 8;
    const int bn   = ((lane >> 4) & 1) * 8 + (lane & 7);
    const int bk   = ((lane >> 3) & 1) * 8;
    #pragma unroll
    for (int g = 0; g < 2; g++) {
        uint32_t a[2][4], b[3][4];
        #pragma unroll
        for (int mt = 0; mt < 2; mt++)
            ldsm4(a[mt], abase + (uint32_t)(((wm * 32 + mt * 16 + arow) * PA + g * 16 + ak) * 2));
        #pragma unroll
        for (int p = 0; p < 3; p++)
            ldsm4(b[p], bbase + (uint32_t)(((wn * 48 + p * 16 + bn) * PBH + g * 16 + bk) * 2));
        #pragma unroll
        for (int mt = 0; mt < 2; mt++)
            #pragma unroll
            for (int nt = 0; nt < 6; nt++)
                mma16(f.c[mt][nt], a[mt][0], a[mt][1], a[mt][2], a[mt][3],
                      b[nt >> 1][(nt & 1) * 2], b[nt >> 1][(nt & 1) * 2 + 1]);
    }
}

// smem layout gemm1 (bytes): A0 @0 (10240), A1 @10240, B0 @20480 (15360), B1 @35840
#define G1_A(b)  ((b) * 10240)
#define G1_B(b)  (20480 + (b) * 15360)
#define GEMM1_SMEM 51200
// smem layout gemm2: W2 @0 (76800), A0 @76800, A1 @87040
#define G2_A(b)  (76800 + (b) * 10240)
#define GEMM2_SMEM 97280

// ---------- stage 1: h = fp16(relu(x @ W1 + b1)) ----------
__global__ void __launch_bounds__(512, 1) gemm1_kernel(
    const float* __restrict__ x, const float* __restrict__ b1)
{
    extern __shared__ char sm[];
    const uint32_t sb = (uint32_t)__cvta_generic_to_shared(sm);
    const int tid  = threadIdx.x;
    const int lane = tid & 31;
    const int wid  = tid >> 5;
    const int wm   = wid & 3, wn = wid >> 2;
    const int row0 = blockIdx.x * 128;
    const int myk  = tid & 31;           // fixed k within chunk for A loads
    const int rb   = tid >> 5;           // row base for A loads

    Frag f;
    #pragma unroll
    for (int mt = 0; mt < 2; mt++)
        #pragma unroll
        for (int nt = 0; nt < 6; nt++)
            #pragma unroll
            for (int q = 0; q < 4; q++) f.c[mt][nt][q] = 0.f;

    // ---- prologue: B0 via cp.async, A0 via LDG+convert+STS ----
    {
        const int i = tid;               // B copy: n=i>>2, j=i&3 (768 total)
        CP16(sb + G1_B(0) + (uint32_t)(((i >> 2) * PB + (i & 3) * 8) * 2),
             g_W1h + (i >> 2) * KPAD1 + (i & 3) * 8);
        const int i2 = tid + 512;
        if (i2 < 768)
            CP16(sb + G1_B(0) + (uint32_t)(((i2 >> 2) * PB + (i2 & 3) * 8) * 2),
                 g_W1h + (i2 >> 2) * KPAD1 + (i2 & 3) * 8);
        CP_COMMIT();
    }
    {
        __half* Ah = (__half*)(sm + G1_A(0));
        const bool kv = (myk < D_INPUT);
        #pragma unroll
        for (int t = 0; t < 8; t++) {
            const int r = rb + t * 16;
            float v = kv ? __ldg(&x[(size_t)(row0 + r) * D_INPUT + myk]) : 0.f;
            Ah[r * PA + myk] = __float2half_rn(v);
        }
    }
    CP_WAIT0();
    __syncthreads();

    for (int c = 0; c < NCH1; c++) {
        const int nx = c + 1;
        float xa[8];
        if (nx < NCH1) {
            const uint32_t bdst = sb + G1_B(nx & 1);
            const int i = tid;
            CP16(bdst + (uint32_t)(((i >> 2) * PB + (i & 3) * 8) * 2),
                 g_W1h + (i >> 2) * KPAD1 + nx * 32 + (i & 3) * 8);
            const int i2 = tid + 512;
            if (i2 < 768)
                CP16(bdst + (uint32_t)(((i2 >> 2) * PB + (i2 & 3) * 8) * 2),
                     g_W1h + (i2 >> 2) * KPAD1 + nx * 32 + (i2 & 3) * 8);
            CP_COMMIT();
            const int k = nx * 32 + myk;
            const bool kv = (k < D_INPUT);
            #pragma unroll
            for (int t = 0; t < 8; t++) {
                const int r = rb + t * 16;
                xa[t] = kv ? __ldg(&x[(size_t)(row0 + r) * D_INPUT + k]) : 0.f;
            }
        }
        compute_chunk<PB>(sb + G1_A(c & 1), sb + G1_B(c & 1), f, wm, wn, lane);
        if (nx < NCH1) {
            __half* Ad = (__half*)(sm + G1_A(nx & 1));
            #pragma unroll
            for (int t = 0; t < 8; t++) {
                const int r = rb + t * 16;
                Ad[r * PA + myk] = __float2half_rn(xa[t]);
            }
            CP_WAIT0();
        }
        __syncthreads();
    }

    // ---- epilogue: g_h = fp16(relu(c + b1)), plain layout ----
    #pragma unroll
    for (int mt = 0; mt < 2; mt++) {
        const int r = row0 + wm * 32 + mt * 16 + (lane >> 2);
        #pragma unroll
        for (int nt = 0; nt < 6; nt++) {
            const int n = wn * 48 + nt * 8 + 2 * (lane & 3);
            const float bb0 = __ldg(&b1[n]), bb1 = __ldg(&b1[n + 1]);
            __half2 v0 = __floats2half2_rn(fmaxf(f.c[mt][nt][0] + bb0, 0.f),
                                           fmaxf(f.c[mt][nt][1] + bb1, 0.f));
            __half2 v1 = __floats2half2_rn(fmaxf(f.c[mt][nt][2] + bb0, 0.f),
                                           fmaxf(f.c[mt][nt][3] + bb1, 0.f));
            g_h[(size_t)r * 96 + (n >> 1)]       = *(uint32_t*)&v0;
            g_h[(size_t)(r + 8) * 96 + (n >> 1)] = *(uint32_t*)&v1;
        }
    }
}

// ---------- stage 2: feat = relu(h @ W2 + b2), W2 fully smem-resident ----------
__global__ void __launch_bounds__(512, 1) gemm2_kernel(const float* __restrict__ b2)
{
    extern __shared__ char sm[];
    const uint32_t sb = (uint32_t)__cvta_generic_to_shared(sm);
    const int tid  = threadIdx.x;
    const int lane = tid & 31;
    const int wid  = tid >> 5;
    const int wm   = wid & 3, wn = wid >> 2;
    const int row0 = blockIdx.x * 128;
    const __half* hsrc = (const __half*)g_h;

    Frag f;
    #pragma unroll
    for (int mt = 0; mt < 2; mt++)
        #pragma unroll
        for (int nt = 0; nt < 6; nt++)
            #pragma unroll
            for (int q = 0; q < 4; q++) f.c[mt][nt][q] = 0.f;

    // ---- prologue: whole W2 (4608 x 16B) + A chunk 0 (512 x 16B) ----
    #pragma unroll
    for (int t = 0; t < 9; t++) {
        const int i = tid + t * 512;               // < 4608
        const int n = i / 24, j = i - n * 24;
        CP16(sb + (uint32_t)((n * PW2 + j * 8) * 2), g_W2h + n * D_H + j * 8);
    }
    {
        const int r = tid >> 2, j = tid & 3;
        CP16(sb + G2_A(0) + (uint32_t)((r * PA + j * 8) * 2),
             hsrc + (size_t)(row0 + r) * D_H + j * 8);
    }
    CP_COMMIT();
    CP_WAIT0();
    __syncthreads();

    for (int c = 0; c < NCH2; c++) {
        const int nx = c + 1;
        if (nx < NCH2) {
            const int r = tid >> 2, j = tid & 3;
            CP16(sb + G2_A(nx & 1) + (uint32_t)((r * PA + j * 8) * 2),
                 hsrc + (size_t)(row0 + r) * D_H + nx * 32 + j * 8);
            CP_COMMIT();
        }
        compute_chunk<PW2>(sb + G2_A(c & 1), sb + (uint32_t)(c * 64), f, wm, wn, lane);
        if (nx < NCH2) CP_WAIT0();
        __syncthreads();
    }

    // ---- epilogue: feat = relu(c + b2), full fp32 ----
    #pragma unroll
    for (int mt = 0; mt < 2; mt++) {
        const int r = row0 + wm * 32 + mt * 16 + (lane >> 2);
        #pragma unroll
        for (int nt = 0; nt < 6; nt++) {
            const int n = wn * 48 + nt * 8 + 2 * (lane & 3);
            const float bb0 = __ldg(&b2[n]), bb1 = __ldg(&b2[n + 1]);
            float2 v0, v1;
            v0.x = fmaxf(f.c[mt][nt][0] + bb0, 0.f);
            v0.y = fmaxf(f.c[mt][nt][1] + bb1, 0.f);
            v1.x = fmaxf(f.c[mt][nt][2] + bb0, 0.f);
            v1.y = fmaxf(f.c[mt][nt][3] + bb1, 0.f);
            *(float2*)&g_feat[(size_t)r * D_H + n]       = v0;
            *(float2*)&g_feat[(size_t)(r + 8) * D_H + n] = v1;
        }
    }
}

// ---------------- binning: histogram -> scan -> scatter ----------------
__global__ void zero_kernel() {
    int i = blockIdx.x * blockDim.x + threadIdx.x;
    if (i < NHEADS) g_cnt[i] = 0;
}

__global__ void hist_kernel(const int* __restrict__ qid, const int* __restrict__ cor) {
    int b = blockIdx.x * blockDim.x + threadIdx.x;
    if (b < B_TOTAL) atomicAdd(&g_cnt[qid[b] + cor[b] * NQ], 1);
}

__global__ void scan_kernel() {   // single block of 1024, Hillis-Steele over 2048
    __shared__ int s[2048];
    const int t = threadIdx.x;
    s[t]        = (t < NHEADS) ? g_cnt[t] : 0;
    s[t + 1024] = (t + 1024 < NHEADS) ? g_cnt[t + 1024] : 0;
    __syncthreads();
    for (int d = 1; d < 2048; d <<= 1) {
        int v0 = s[t], v1 = s[t + 1024];
        int a0 = (t >= d) ? s[t - d] : 0;
        int a1 = (t + 1024 >= d) ? s[t + 1024 - d] : 0;
        __syncthreads();
        s[t] = v0 + a0;
        s[t + 1024] = v1 + a1;
        __syncthreads();
    }
    if (t < NHEADS)          { int e = (t == 0) ? 0 : s[t - 1]; g_off[t] = e; g_cur[t] = e; }
    if (t + 1024 < NHEADS)   { int e = s[t + 1023];             g_off[t + 1024] = e; g_cur[t + 1024] = e; }
    if (t == 0) g_off[NHEADS] = s[NHEADS - 1];
}

__global__ void scatter_kernel(const int* __restrict__ qid, const int* __restrict__ cor) {
    int b = blockIdx.x * blockDim.x + threadIdx.x;
    if (b < B_TOTAL) {
        int h = qid[b] + cor[b] * NQ;
        int p = atomicAdd(&g_cur[h], 1);
        g_order[p] = b;
    }
}

// ---------------- routed heads: one CTA per head group ----------------
__global__ void __launch_bounds__(256) heads_kernel(
    const float* __restrict__ Wh, const float* __restrict__ bh, float* __restrict__ out)
{
    const int g = blockIdx.x;
    const int t = threadIdx.x;
    const int c = t & 15, j = t >> 4;

    __shared__ float s_feat[D_H];
    __shared__ float s_part[256];
    __shared__ float s_bq[NC];

    float w[12];
    const float* wp = Wh + ((size_t)g * NC + c) * D_H + j * 12;
    #pragma unroll
    for (int u = 0; u < 12; u++) w[u] = wp[u];
    if (t < NC) s_bq[t] = bh[g * NC + t];

    const int start = g_off[g], end = g_off[g + 1];

    float nxt = 0.f;
    if (start < end && t < D_H) nxt = g_feat[(size_t)g_order[start] * D_H + t];
    __syncthreads();

    for (int s = start; s < end; s++) {
        if (t < D_H) s_feat[t] = nxt;
        __syncthreads();
        if (s + 1 < end && t < D_H)
            nxt = g_feat[(size_t)g_order[s + 1] * D_H + t];
        float p = 0.f;
        const float* f = s_feat + j * 12;
        #pragma unroll
        for (int u = 0; u < 12; u++) p += w[u] * f[u];
        s_part[t] = p;
        __syncthreads();
        if (t < NC) {
            float sum = s_bq[t];
            #pragma unroll
            for (int jj = 0; jj < 16; jj++) sum += s_part[t + 16 * jj];
            out[(size_t)g_order[s] * NC + t] = sum;
        }
        __syncthreads();
    }
}

// ---------------- launch ----------------
extern "C" void kernel_launch(void* const* d_in, const int* in_sizes, int n_in,
                              void* d_out, int out_size) {
    const float* x   = (const float*)d_in[0];
    const int*   qid = (const int*)d_in[1];
    const int*   cor = (const int*)d_in[2];
    const float* W1  = (const float*)d_in[3];
    const float* b1  = (const float*)d_in[4];
    const float* W2  = (const float*)d_in[5];
    const float* b2  = (const float*)d_in[6];
    const float* Wh  = (const float*)d_in[7];
    const float* bh  = (const float*)d_in[8];
    float* out = (float*)d_out;

    cudaFuncSetAttribute(gemm1_kernel, cudaFuncAttributeMaxDynamicSharedMemorySize, GEMM1_SMEM);
    cudaFuncSetAttribute(gemm2_kernel, cudaFuncAttributeMaxDynamicSharedMemorySize, GEMM2_SMEM);

    // order chosen so gemm1 is the 4th launch (profiler window)
    zero_kernel<<<(NHEADS + 255) / 256, 256>>>();
    hist_kernel<<<(B_TOTAL + 255) / 256, 256>>>(qid, cor);
    prep_kernel<<<(D_H * KPAD1 + D_H * D_H + 255) / 256, 256>>>(W1, W2);
    gemm1_kernel<<<B_TOTAL / 128, 512, GEMM1_SMEM>>>(x, b1);
    gemm2_kernel<<<B_TOTAL / 128, 512, GEMM2_SMEM>>>(b2);
    scan_kernel<<<1, 1024>>>();
    scatter_kernel<<<(B_TOTAL + 255) / 256, 256>>>(qid, cor);
    heads_kernel<<<NHEADS, 256>>>(Wh, bh, out);
}

// round 6
// speedup vs baseline: 2.0134x; 1.0687x over previous
#include <cuda_runtime.h>
#include <cuda_fp16.h>
#include <cstdint>
#include <cstddef>

// ---------------- problem constants ----------------
#define B_TOTAL 131072
#define D_INPUT 385
#define D_H     192
#define NQ      1000
#define NHEADS  2000
#define NC      16

#define KPAD1   416            // 13 chunks of 32
#define NCH1    13
#define NCH2    6
#define PA      40             // A smem pitch (halves); 80B row stride -> LDSM conflict-free
#define PB      40             // B smem pitch (halves), gemm1
#define PW2     200            // W2 smem pitch (halves), gemm2; 400B stride -> conflict-free

// ---------------- scratch (device globals: allocation-free) ----------------
__device__ uint32_t g_h[(size_t)B_TOTAL * 96];       // hidden fp16, plain [r][192], 50 MB
__device__ uint32_t g_feat16[(size_t)B_TOTAL * 96];  // trunk output fp16, 50 MB
__device__ __half   g_W1h[D_H * KPAD1];              // W1^T fp16 [n][KPAD1], zero-padded
__device__ __half   g_W2h[D_H * D_H];                // W2^T fp16 [n][192]
__device__ int      g_cnt[NHEADS];
__device__ int      g_off[NHEADS + 1];
__device__ int      g_cur[NHEADS];
__device__ int      g_order[B_TOTAL];

// ---------------- PTX helpers ----------------
#define CP16(dst, src) \
    asm volatile("cp.async.cg.shared.global [%0], [%1], 16;" \
                 :: "r"(dst), "l"(__cvta_generic_to_global((const void*)(src))))
#define CP_COMMIT() asm volatile("cp.async.commit_group;" ::: "memory")
#define CP_WAIT0()  asm volatile("cp.async.wait_group 0;" ::: "memory")

__device__ __forceinline__ void ldsm4(uint32_t r[4], uint32_t addr) {
    asm volatile("ldmatrix.sync.aligned.m8n8.x4.shared.b16 {%0,%1,%2,%3}, [%4];"
        : "=r"(r[0]), "=r"(r[1]), "=r"(r[2]), "=r"(r[3]) : "r"(addr));
}

__device__ __forceinline__ void mma16(float c[4], uint32_t a0, uint32_t a1,
                                      uint32_t a2, uint32_t a3, uint32_t b0, uint32_t b1) {
    asm volatile(
        "mma.sync.aligned.m16n8k16.row.col.f32.f16.f16.f32 "
        "{%0,%1,%2,%3}, {%4,%5,%6,%7}, {%8,%9}, {%0,%1,%2,%3};\n"
        : "+f"(c[0]), "+f"(c[1]), "+f"(c[2]), "+f"(c[3])
        : "r"(a0), "r"(a1), "r"(a2), "r"(a3), "r"(b0), "r"(b1));
}

// ---------------- prep: W1/W2 -> transposed fp16 (plain layout) ----------------
__global__ void prep_kernel(const float* __restrict__ W1, const float* __restrict__ W2) {
    int i = blockIdx.x * blockDim.x + threadIdx.x;
    const int T1 = D_H * KPAD1;
    if (i < T1) {
        int n = i / KPAD1, k = i - n * KPAD1;
        float v = (k < D_INPUT) ? W1[(size_t)k * D_H + n] : 0.f;
        g_W1h[i] = __float2half_rn(v);
    } else {
        int j = i - T1;
        if (j < D_H * D_H) {
            int n = j / D_H, k = j - n * D_H;
            g_W2h[j] = __float2half_rn(W2[(size_t)k * D_H + n]);
        }
    }
}

// ---------------- GEMM core ----------------
// 256 threads = 8 warps: wm = wid&1 (M, 32 rows), wn = wid>>1 (N, 48 cols).
// CTA tile 64x192, 2 CTAs/SM. Fragments via ldmatrix.x4, fp16 m16n8k16.
struct Frag { float c[2][6][4]; };

template<int PBH>
__device__ __forceinline__ void compute_chunk(uint32_t abase, uint32_t bbase,
                                              Frag& f, int wm, int wn, int lane)
{
    const int arow = ((lane >> 3) & 1) * 8 + (lane & 7);
    const int ak   = (lane >> 4) * 8;
    const int bn   = ((lane >> 4) & 1) * 8 + (lane & 7);
    const int bk   = ((lane >> 3) & 1) * 8;
    #pragma unroll
    for (int g = 0; g < 2; g++) {
        uint32_t a[2][4], b[3][4];
        #pragma unroll
        for (int mt = 0; mt < 2; mt++)
            ldsm4(a[mt], abase + (uint32_t)(((wm * 32 + mt * 16 + arow) * PA + g * 16 + ak) * 2));
        #pragma unroll
        for (int p = 0; p < 3; p++)
            ldsm4(b[p], bbase + (uint32_t)(((wn * 48 + p * 16 + bn) * PBH + g * 16 + bk) * 2));
        #pragma unroll
        for (int mt = 0; mt < 2; mt++)
            #pragma unroll
            for (int nt = 0; nt < 6; nt++)
                mma16(f.c[mt][nt], a[mt][0], a[mt][1], a[mt][2], a[mt][3],
                      b[nt >> 1][(nt & 1) * 2], b[nt >> 1][(nt & 1) * 2 + 1]);
    }
}

// smem layout gemm1 (bytes): A0 @0 (5120), A1 @5120, B0 @10240 (15360), B1 @25600
#define G1_A(b)  ((b) * 5120)
#define G1_B(b)  (10240 + (b) * 15360)
#define GEMM1_SMEM 40960
// smem layout gemm2: W2 @0 (76800), A0 @76800 (5120), A1 @81920
#define G2_A(b)  (76800 + (b) * 5120)
#define GEMM2_SMEM 87040

// ---------- stage 1: h = fp16(relu(x @ W1 + b1)) ----------
__global__ void __launch_bounds__(256, 2) gemm1_kernel(
    const float* __restrict__ x, const float* __restrict__ b1)
{
    extern __shared__ char sm[];
    const uint32_t sb = (uint32_t)__cvta_generic_to_shared(sm);
    const int tid  = threadIdx.x;
    const int lane = tid & 31;
    const int wid  = tid >> 5;
    const int wm   = wid & 1, wn = wid >> 1;
    const int row0 = blockIdx.x * 64;
    const int myk  = tid & 31;           // fixed k within chunk for A loads
    const int rb   = tid >> 5;           // row base for A loads (0..7)

    Frag f;
    #pragma unroll
    for (int mt = 0; mt < 2; mt++)
        #pragma unroll
        for (int nt = 0; nt < 6; nt++)
            #pragma unroll
            for (int q = 0; q < 4; q++) f.c[mt][nt][q] = 0.f;

    // ---- prologue: B0 via cp.async (768 segs), A0 via LDG+convert+STS ----
    {
        #pragma unroll
        for (int t = 0; t < 3; t++) {
            const int i = tid + t * 256;
            CP16(sb + G1_B(0) + (uint32_t)(((i >> 2) * PB + (i & 3) * 8) * 2),
                 g_W1h + (i >> 2) * KPAD1 + (i & 3) * 8);
        }
        CP_COMMIT();
    }
    {
        __half* Ah = (__half*)(sm + G1_A(0));
        const bool kv = (myk < D_INPUT);
        #pragma unroll
        for (int t = 0; t < 8; t++) {
            const int r = rb + t * 8;
            float v = kv ? __ldg(&x[(size_t)(row0 + r) * D_INPUT + myk]) : 0.f;
            Ah[r * PA + myk] = __float2half_rn(v);
        }
    }
    CP_WAIT0();
    __syncthreads();

    for (int c = 0; c < NCH1; c++) {
        const int nx = c + 1;
        float xa[8];
        if (nx < NCH1) {
            const uint32_t bdst = sb + G1_B(nx & 1);
            #pragma unroll
            for (int t = 0; t < 3; t++) {
                const int i = tid + t * 256;
                CP16(bdst + (uint32_t)(((i >> 2) * PB + (i & 3) * 8) * 2),
                     g_W1h + (i >> 2) * KPAD1 + nx * 32 + (i & 3) * 8);
            }
            CP_COMMIT();
            const int k = nx * 32 + myk;
            const bool kv = (k < D_INPUT);
            #pragma unroll
            for (int t = 0; t < 8; t++) {
                const int r = rb + t * 8;
                xa[t] = kv ? __ldg(&x[(size_t)(row0 + r) * D_INPUT + k]) : 0.f;
            }
        }
        compute_chunk<PB>(sb + G1_A(c & 1), sb + G1_B(c & 1), f, wm, wn, lane);
        if (nx < NCH1) {
            __half* Ad = (__half*)(sm + G1_A(nx & 1));
            #pragma unroll
            for (int t = 0; t < 8; t++) {
                const int r = rb + t * 8;
                Ad[r * PA + myk] = __float2half_rn(xa[t]);
            }
            CP_WAIT0();
        }
        __syncthreads();
    }

    // ---- epilogue: g_h = fp16(relu(c + b1)), plain layout ----
    #pragma unroll
    for (int mt = 0; mt < 2; mt++) {
        const int r = row0 + wm * 32 + mt * 16 + (lane >> 2);
        #pragma unroll
        for (int nt = 0; nt < 6; nt++) {
            const int n = wn * 48 + nt * 8 + 2 * (lane & 3);
            const float bb0 = __ldg(&b1[n]), bb1 = __ldg(&b1[n + 1]);
            __half2 v0 = __floats2half2_rn(fmaxf(f.c[mt][nt][0] + bb0, 0.f),
                                           fmaxf(f.c[mt][nt][1] + bb1, 0.f));
            __half2 v1 = __floats2half2_rn(fmaxf(f.c[mt][nt][2] + bb0, 0.f),
                                           fmaxf(f.c[mt][nt][3] + bb1, 0.f));
            g_h[(size_t)r * 96 + (n >> 1)]       = *(uint32_t*)&v0;
            g_h[(size_t)(r + 8) * 96 + (n >> 1)] = *(uint32_t*)&v1;
        }
    }
}

// ---------- stage 2: feat16 = fp16(relu(h @ W2 + b2)), W2 fully smem-resident ----------
__global__ void __launch_bounds__(256, 2) gemm2_kernel(const float* __restrict__ b2)
{
    extern __shared__ char sm[];
    const uint32_t sb = (uint32_t)__cvta_generic_to_shared(sm);
    const int tid  = threadIdx.x;
    const int lane = tid & 31;
    const int wid  = tid >> 5;
    const int wm   = wid & 1, wn = wid >> 1;
    const int row0 = blockIdx.x * 64;
    const __half* hsrc = (const __half*)g_h;

    Frag f;
    #pragma unroll
    for (int mt = 0; mt < 2; mt++)
        #pragma unroll
        for (int nt = 0; nt < 6; nt++)
            #pragma unroll
            for (int q = 0; q < 4; q++) f.c[mt][nt][q] = 0.f;

    // ---- prologue: whole W2 (4608 x 16B) + A chunk 0 (256 x 16B) ----
    #pragma unroll
    for (int t = 0; t < 18; t++) {
        const int i = tid + t * 256;               // < 4608
        const int n = i / 24, j = i - n * 24;
        CP16(sb + (uint32_t)((n * PW2 + j * 8) * 2), g_W2h + n * D_H + j * 8);
    }
    {
        const int r = tid >> 2, j = tid & 3;
        CP16(sb + G2_A(0) + (uint32_t)((r * PA + j * 8) * 2),
             hsrc + (size_t)(row0 + r) * D_H + j * 8);
    }
    CP_COMMIT();
    CP_WAIT0();
    __syncthreads();

    for (int c = 0; c < NCH2; c++) {
        const int nx = c + 1;
        if (nx < NCH2) {
            const int r = tid >> 2, j = tid & 3;
            CP16(sb + G2_A(nx & 1) + (uint32_t)((r * PA + j * 8) * 2),
                 hsrc + (size_t)(row0 + r) * D_H + nx * 32 + j * 8);
            CP_COMMIT();
        }
        compute_chunk<PW2>(sb + G2_A(c & 1), sb + (uint32_t)(c * 64), f, wm, wn, lane);
        if (nx < NCH2) CP_WAIT0();
        __syncthreads();
    }

    // ---- epilogue: feat16 = fp16(relu(c + b2)) ----
    #pragma unroll
    for (int mt = 0; mt < 2; mt++) {
        const int r = row0 + wm * 32 + mt * 16 + (lane >> 2);
        #pragma unroll
        for (int nt = 0; nt < 6; nt++) {
            const int n = wn * 48 + nt * 8 + 2 * (lane & 3);
            const float bb0 = __ldg(&b2[n]), bb1 = __ldg(&b2[n + 1]);
            __half2 v0 = __floats2half2_rn(fmaxf(f.c[mt][nt][0] + bb0, 0.f),
                                           fmaxf(f.c[mt][nt][1] + bb1, 0.f));
            __half2 v1 = __floats2half2_rn(fmaxf(f.c[mt][nt][2] + bb0, 0.f),
                                           fmaxf(f.c[mt][nt][3] + bb1, 0.f));
            g_feat16[(size_t)r * 96 + (n >> 1)]       = *(uint32_t*)&v0;
            g_feat16[(size_t)(r + 8) * 96 + (n >> 1)] = *(uint32_t*)&v1;
        }
    }
}

// ---------------- binning: histogram -> scan -> scatter ----------------
__global__ void zero_kernel() {
    int i = blockIdx.x * blockDim.x + threadIdx.x;
    if (i < NHEADS) g_cnt[i] = 0;
}

__global__ void hist_kernel(const int* __restrict__ qid, const int* __restrict__ cor) {
    int b = blockIdx.x * blockDim.x + threadIdx.x;
    if (b < B_TOTAL) atomicAdd(&g_cnt[qid[b] + cor[b] * NQ], 1);
}

__global__ void scan_kernel() {   // single block of 1024, Hillis-Steele over 2048
    __shared__ int s[2048];
    const int t = threadIdx.x;
    s[t]        = (t < NHEADS) ? g_cnt[t] : 0;
    s[t + 1024] = (t + 1024 < NHEADS) ? g_cnt[t + 1024] : 0;
    __syncthreads();
    for (int d = 1; d < 2048; d <<= 1) {
        int v0 = s[t], v1 = s[t + 1024];
        int a0 = (t >= d) ? s[t - d] : 0;
        int a1 = (t + 1024 >= d) ? s[t + 1024 - d] : 0;
        __syncthreads();
        s[t] = v0 + a0;
        s[t + 1024] = v1 + a1;
        __syncthreads();
    }
    if (t < NHEADS)          { int e = (t == 0) ? 0 : s[t - 1]; g_off[t] = e; g_cur[t] = e; }
    if (t + 1024 < NHEADS)   { int e = s[t + 1023];             g_off[t + 1024] = e; g_cur[t + 1024] = e; }
    if (t == 0) g_off[NHEADS] = s[NHEADS - 1];
}

__global__ void scatter_kernel(const int* __restrict__ qid, const int* __restrict__ cor) {
    int b = blockIdx.x * blockDim.x + threadIdx.x;
    if (b < B_TOTAL) {
        int h = qid[b] + cor[b] * NQ;
        int p = atomicAdd(&g_cur[h], 1);
        g_order[p] = b;
    }
}

// ---------------- routed heads: one CTA per head group ----------------
__global__ void __launch_bounds__(256) heads_kernel(
    const float* __restrict__ Wh, const float* __restrict__ bh, float* __restrict__ out)
{
    const int g = blockIdx.x;
    const int t = threadIdx.x;
    const int c = t & 15, j = t >> 4;

    __shared__ float s_feat[D_H];
    __shared__ float s_part[256];
    __shared__ float s_bq[NC];

    float w[12];
    const float* wp = Wh + ((size_t)g * NC + c) * D_H + j * 12;
    #pragma unroll
    for (int u = 0; u < 12; u++) w[u] = wp[u];
    if (t < NC) s_bq[t] = bh[g * NC + t];

    const int start = g_off[g], end = g_off[g + 1];

    uint32_t nxt = 0;
    if (start < end && t < 96) nxt = g_feat16[(size_t)g_order[start] * 96 + t];
    __syncthreads();

    for (int s = start; s < end; s++) {
        if (t < 96) {
            const __half2 hh = *(const __half2*)&nxt;
            const float2 fv = __half22float2(hh);
            s_feat[2 * t]     = fv.x;
            s_feat[2 * t + 1] = fv.y;
        }
        __syncthreads();
        if (s + 1 < end && t < 96)
            nxt = g_feat16[(size_t)g_order[s + 1] * 96 + t];
        float p = 0.f;
        const float* f = s_feat + j * 12;
        #pragma unroll
        for (int u = 0; u < 12; u++) p += w[u] * f[u];
        s_part[t] = p;
        __syncthreads();
        if (t < NC) {
            float sum = s_bq[t];
            #pragma unroll
            for (int jj = 0; jj < 16; jj++) sum += s_part[t + 16 * jj];
            out[(size_t)g_order[s] * NC + t] = sum;
        }
        __syncthreads();
    }
}

// ---------------- launch ----------------
extern "C" void kernel_launch(void* const* d_in, const int* in_sizes, int n_in,
                              void* d_out, int out_size) {
    const float* x   = (const float*)d_in[0];
    const int*   qid = (const int*)d_in[1];
    const int*   cor = (const int*)d_in[2];
    const float* W1  = (const float*)d_in[3];
    const float* b1  = (const float*)d_in[4];
    const float* W2  = (const float*)d_in[5];
    const float* b2  = (const float*)d_in[6];
    const float* Wh  = (const float*)d_in[7];
    const float* bh  = (const float*)d_in[8];
    float* out = (float*)d_out;

    cudaFuncSetAttribute(gemm1_kernel, cudaFuncAttributeMaxDynamicSharedMemorySize, GEMM1_SMEM);
    cudaFuncSetAttribute(gemm2_kernel, cudaFuncAttributeMaxDynamicSharedMemorySize, GEMM2_SMEM);

    // order chosen so gemm1 is the 4th launch (profiler window)
    zero_kernel<<<(NHEADS + 255) / 256, 256>>>();
    hist_kernel<<<(B_TOTAL + 255) / 256, 256>>>(qid, cor);
    prep_kernel<<<(D_H * KPAD1 + D_H * D_H + 255) / 256, 256>>>(W1, W2);
    gemm1_kernel<<<B_TOTAL / 64, 256, GEMM1_SMEM>>>(x, b1);
    gemm2_kernel<<<B_TOTAL / 64, 256, GEMM2_SMEM>>>(b2);
    scan_kernel<<<1, 1024>>>();
    scatter_kernel<<<(B_TOTAL + 255) / 256, 256>>>(qid, cor);
    heads_kernel<<<NHEADS, 256>>>(Wh, bh, out);
}

// round 7
// speedup vs baseline: 2.1776x; 1.0815x over previous
#include <cuda_runtime.h>
#include <cuda_fp16.h>
#include <cstdint>
#include <cstddef>

// ---------------- problem constants ----------------
#define B_TOTAL 131072
#define D_INPUT 385
#define D_H     192
#define NQ      1000
#define NHEADS  2000
#define NC      16

#define KPAD1   416            // 13 chunks of 32
#define NCH1    13
#define NCH2    6
#define PA      40             // A/H smem pitch (halves); 80B row stride -> LDSM conflict-free
#define PB      40             // B smem pitch (halves)

// ---------------- scratch (device globals: allocation-free) ----------------
__device__ uint32_t g_feat16[(size_t)B_TOTAL * 96];  // trunk output fp16, 50 MB
__device__ __half   g_W1h[D_H * KPAD1];              // W1^T fp16 [n][KPAD1], zero-padded
__device__ __half   g_W2h[D_H * D_H];                // W2^T fp16 [n][192]
__device__ int      g_cnt[NHEADS];
__device__ int      g_off[NHEADS + 1];
__device__ int      g_cur[NHEADS];
__device__ int      g_order[B_TOTAL];

// ---------------- PTX helpers ----------------
#define CP16(dst, src) \
    asm volatile("cp.async.cg.shared.global [%0], [%1], 16;" \
                 :: "r"(dst), "l"(__cvta_generic_to_global((const void*)(src))))
#define CP_COMMIT() asm volatile("cp.async.commit_group;" ::: "memory")
#define CP_WAIT0()  asm volatile("cp.async.wait_group 0;" ::: "memory")

__device__ __forceinline__ void ldsm4(uint32_t r[4], uint32_t addr) {
    asm volatile("ldmatrix.sync.aligned.m8n8.x4.shared.b16 {%0,%1,%2,%3}, [%4];"
        : "=r"(r[0]), "=r"(r[1]), "=r"(r[2]), "=r"(r[3]) : "r"(addr));
}

__device__ __forceinline__ void mma16(float c[4], uint32_t a0, uint32_t a1,
                                      uint32_t a2, uint32_t a3, uint32_t b0, uint32_t b1) {
    asm volatile(
        "mma.sync.aligned.m16n8k16.row.col.f32.f16.f16.f32 "
        "{%0,%1,%2,%3}, {%4,%5,%6,%7}, {%8,%9}, {%0,%1,%2,%3};\n"
        : "+f"(c[0]), "+f"(c[1]), "+f"(c[2]), "+f"(c[3])
        : "r"(a0), "r"(a1), "r"(a2), "r"(a3), "r"(b0), "r"(b1));
}

// ---------------- prep: W1/W2 -> transposed fp16 (plain layout) ----------------
__global__ void prep_kernel(const float* __restrict__ W1, const float* __restrict__ W2) {
    int i = blockIdx.x * blockDim.x + threadIdx.x;
    const int T1 = D_H * KPAD1;
    if (i < T1) {
        int n = i / KPAD1, k = i - n * KPAD1;
        float v = (k < D_INPUT) ? W1[(size_t)k * D_H + n] : 0.f;
        g_W1h[i] = __float2half_rn(v);
    } else {
        int j = i - T1;
        if (j < D_H * D_H) {
            int n = j / D_H, k = j - n * D_H;
            g_W2h[j] = __float2half_rn(W2[(size_t)k * D_H + n]);
        }
    }
}

// ---------------- fused trunk ----------------
// 256 threads = 8 warps: wm = wid&1 (M, 32 rows), wn = wid>>1 (N, 48 cols).
// CTA tile 64x192, 2 CTAs/SM. Fragments via ldmatrix.x4, fp16 m16n8k16.
// Phase 1: h = relu(x@W1+b1) -> smem H blocks.  Phase 2: feat = relu(H@W2+b2).
struct Frag { float c[2][6][4]; };

__device__ __forceinline__ void compute_chunk(uint32_t abase, uint32_t bbase,
                                              Frag& f, int wm, int wn, int lane)
{
    const int arow = ((lane >> 3) & 1) * 8 + (lane & 7);
    const int ak   = (lane >> 4) * 8;
    const int bn   = ((lane >> 4) & 1) * 8 + (lane & 7);
    const int bk   = ((lane >> 3) & 1) * 8;
    #pragma unroll
    for (int g = 0; g < 2; g++) {
        uint32_t a[2][4], b[3][4];
        #pragma unroll
        for (int mt = 0; mt < 2; mt++)
            ldsm4(a[mt], abase + (uint32_t)(((wm * 32 + mt * 16 + arow) * PA + g * 16 + ak) * 2));
        #pragma unroll
        for (int p = 0; p < 3; p++)
            ldsm4(b[p], bbase + (uint32_t)(((wn * 48 + p * 16 + bn) * PB + g * 16 + bk) * 2));
        #pragma unroll
        for (int mt = 0; mt < 2; mt++)
            #pragma unroll
            for (int nt = 0; nt < 6; nt++)
                mma16(f.c[mt][nt], a[mt][0], a[mt][1], a[mt][2], a[mt][3],
                      b[nt >> 1][(nt & 1) * 2], b[nt >> 1][(nt & 1) * 2 + 1]);
    }
}

// smem layout (bytes): A0 @0 (5120), A1 @5120, B0 @10240 (15360), B1 @25600,
//                      H blocks @40960 (6 x 5120)
#define SM_A(b)  ((b) * 5120)
#define SM_B(b)  (10240 + (b) * 15360)
#define SM_H(c)  (40960 + (c) * 5120)
#define FUSED_SMEM 71680

__global__ void __launch_bounds__(256, 2) trunk_kernel(
    const float* __restrict__ x, const float* __restrict__ b1, const float* __restrict__ b2)
{
    extern __shared__ char sm[];
    const uint32_t sb = (uint32_t)__cvta_generic_to_shared(sm);
    const int tid  = threadIdx.x;
    const int lane = tid & 31;
    const int wid  = tid >> 5;
    const int wm   = wid & 1, wn = wid >> 1;
    const int row0 = blockIdx.x * 64;
    const int myk  = tid & 31;           // fixed k within chunk for A loads
    const int rb   = tid >> 5;           // row base for A loads (0..7)

    Frag f;
    #pragma unroll
    for (int mt = 0; mt < 2; mt++)
        #pragma unroll
        for (int nt = 0; nt < 6; nt++)
            #pragma unroll
            for (int q = 0; q < 4; q++) f.c[mt][nt][q] = 0.f;

    // ================= phase 1: h = relu(x @ W1 + b1) =================
    // prologue: B0 via cp.async (768 segs), A0 via LDG+convert+STS
    {
        #pragma unroll
        for (int t = 0; t < 3; t++) {
            const int i = tid + t * 256;
            CP16(sb + SM_B(0) + (uint32_t)(((i >> 2) * PB + (i & 3) * 8) * 2),
                 g_W1h + (i >> 2) * KPAD1 + (i & 3) * 8);
        }
        CP_COMMIT();
    }
    {
        __half* Ah = (__half*)(sm + SM_A(0));
        const bool kv = (myk < D_INPUT);
        #pragma unroll
        for (int t = 0; t < 8; t++) {
            const int r = rb + t * 8;
            float v = kv ? __ldg(&x[(size_t)(row0 + r) * D_INPUT + myk]) : 0.f;
            Ah[r * PA + myk] = __float2half_rn(v);
        }
    }
    CP_WAIT0();
    __syncthreads();

    for (int c = 0; c < NCH1; c++) {
        const int nx = c + 1;
        float xa[8];
        if (nx < NCH1) {
            const uint32_t bdst = sb + SM_B(nx & 1);
            #pragma unroll
            for (int t = 0; t < 3; t++) {
                const int i = tid + t * 256;
                CP16(bdst + (uint32_t)(((i >> 2) * PB + (i & 3) * 8) * 2),
                     g_W1h + (i >> 2) * KPAD1 + nx * 32 + (i & 3) * 8);
            }
            CP_COMMIT();
            const int k = nx * 32 + myk;
            const bool kv = (k < D_INPUT);
            #pragma unroll
            for (int t = 0; t < 8; t++) {
                const int r = rb + t * 8;
                xa[t] = kv ? __ldg(&x[(size_t)(row0 + r) * D_INPUT + k]) : 0.f;
            }
        }
        compute_chunk(sb + SM_A(c & 1), sb + SM_B(c & 1), f, wm, wn, lane);
        if (nx < NCH1) {
            __half* Ad = (__half*)(sm + SM_A(nx & 1));
            #pragma unroll
            for (int t = 0; t < 8; t++) {
                const int r = rb + t * 8;
                Ad[r * PA + myk] = __float2half_rn(xa[t]);
            }
            CP_WAIT0();
        }
        __syncthreads();
    }

    // ---- prefetch W2 chunk 0 into B0 (overlaps epilogue 1) ----
    {
        #pragma unroll
        for (int t = 0; t < 3; t++) {
            const int i = tid + t * 256;
            CP16(sb + SM_B(0) + (uint32_t)(((i >> 2) * PB + (i & 3) * 8) * 2),
                 g_W2h + (i >> 2) * D_H + (i & 3) * 8);
        }
        CP_COMMIT();
    }

    // ---- epilogue 1: H blocks = fp16(relu(c + b1)) in smem ----
    #pragma unroll
    for (int mt = 0; mt < 2; mt++) {
        const int r = wm * 32 + mt * 16 + (lane >> 2);
        #pragma unroll
        for (int nt = 0; nt < 6; nt++) {
            const int n = wn * 48 + nt * 8 + 2 * (lane & 3);
            const float bb0 = __ldg(&b1[n]), bb1 = __ldg(&b1[n + 1]);
            __half2 v0 = __floats2half2_rn(fmaxf(f.c[mt][nt][0] + bb0, 0.f),
                                           fmaxf(f.c[mt][nt][1] + bb1, 0.f));
            __half2 v1 = __floats2half2_rn(fmaxf(f.c[mt][nt][2] + bb0, 0.f),
                                           fmaxf(f.c[mt][nt][3] + bb1, 0.f));
            const uint32_t off = (uint32_t)(SM_H(n >> 5) + (r * PA + (n & 31)) * 2);
            *(uint32_t*)(sm + off)       = *(uint32_t*)&v0;
            *(uint32_t*)(sm + off + PA * 16) = *(uint32_t*)&v1;   // (+8 rows)*PA*2 bytes
        }
    }

    // reset accumulators for phase 2
    #pragma unroll
    for (int mt = 0; mt < 2; mt++)
        #pragma unroll
        for (int nt = 0; nt < 6; nt++)
            #pragma unroll
            for (int q = 0; q < 4; q++) f.c[mt][nt][q] = 0.f;

    CP_WAIT0();
    __syncthreads();

    // ================= phase 2: feat = relu(H @ W2 + b2) =================
    for (int c = 0; c < NCH2; c++) {
        const int nx = c + 1;
        if (nx < NCH2) {
            const uint32_t bdst = sb + SM_B(nx & 1);
            #pragma unroll
            for (int t = 0; t < 3; t++) {
                const int i = tid + t * 256;
                CP16(bdst + (uint32_t)(((i >> 2) * PB + (i & 3) * 8) * 2),
                     g_W2h + (i >> 2) * D_H + nx * 32 + (i & 3) * 8);
            }
            CP_COMMIT();
        }
        compute_chunk(sb + SM_H(c), sb + SM_B(c & 1), f, wm, wn, lane);
        if (nx < NCH2) CP_WAIT0();
        __syncthreads();
    }

    // ---- epilogue 2: g_feat16 = fp16(relu(c + b2)) ----
    #pragma unroll
    for (int mt = 0; mt < 2; mt++) {
        const int r = row0 + wm * 32 + mt * 16 + (lane >> 2);
        #pragma unroll
        for (int nt = 0; nt < 6; nt++) {
            const int n = wn * 48 + nt * 8 + 2 * (lane & 3);
            const float bb0 = __ldg(&b2[n]), bb1 = __ldg(&b2[n + 1]);
            __half2 v0 = __floats2half2_rn(fmaxf(f.c[mt][nt][0] + bb0, 0.f),
                                           fmaxf(f.c[mt][nt][1] + bb1, 0.f));
            __half2 v1 = __floats2half2_rn(fmaxf(f.c[mt][nt][2] + bb0, 0.f),
                                           fmaxf(f.c[mt][nt][3] + bb1, 0.f));
            g_feat16[(size_t)r * 96 + (n >> 1)]       = *(uint32_t*)&v0;
            g_feat16[(size_t)(r + 8) * 96 + (n >> 1)] = *(uint32_t*)&v1;
        }
    }
}

// ---------------- binning: histogram -> scan -> scatter ----------------
__global__ void zero_kernel() {
    int i = blockIdx.x * blockDim.x + threadIdx.x;
    if (i < NHEADS) g_cnt[i] = 0;
}

__global__ void hist_kernel(const int* __restrict__ qid, const int* __restrict__ cor) {
    int b = blockIdx.x * blockDim.x + threadIdx.x;
    if (b < B_TOTAL) atomicAdd(&g_cnt[qid[b] + cor[b] * NQ], 1);
}

__global__ void scan_kernel() {   // single block of 1024, Hillis-Steele over 2048
    __shared__ int s[2048];
    const int t = threadIdx.x;
    s[t]        = (t < NHEADS) ? g_cnt[t] : 0;
    s[t + 1024] = (t + 1024 < NHEADS) ? g_cnt[t + 1024] : 0;
    __syncthreads();
    for (int d = 1; d < 2048; d <<= 1) {
        int v0 = s[t], v1 = s[t + 1024];
        int a0 = (t >= d) ? s[t - d] : 0;
        int a1 = (t + 1024 >= d) ? s[t + 1024 - d] : 0;
        __syncthreads();
        s[t] = v0 + a0;
        s[t + 1024] = v1 + a1;
        __syncthreads();
    }
    if (t < NHEADS)          { int e = (t == 0) ? 0 : s[t - 1]; g_off[t] = e; g_cur[t] = e; }
    if (t + 1024 < NHEADS)   { int e = s[t + 1023];             g_off[t + 1024] = e; g_cur[t + 1024] = e; }
    if (t == 0) g_off[NHEADS] = s[NHEADS - 1];
}

__global__ void scatter_kernel(const int* __restrict__ qid, const int* __restrict__ cor) {
    int b = blockIdx.x * blockDim.x + threadIdx.x;
    if (b < B_TOTAL) {
        int h = qid[b] + cor[b] * NQ;
        int p = atomicAdd(&g_cur[h], 1);
        g_order[p] = b;
    }
}

// ---------------- routed heads: one CTA per head group ----------------
__global__ void __launch_bounds__(256) heads_kernel(
    const float* __restrict__ Wh, const float* __restrict__ bh, float* __restrict__ out)
{
    const int g = blockIdx.x;
    const int t = threadIdx.x;
    const int c = t & 15, j = t >> 4;

    __shared__ float s_feat[D_H];
    __shared__ float s_part[256];
    __shared__ float s_bq[NC];

    float w[12];
    const float* wp = Wh + ((size_t)g * NC + c) * D_H + j * 12;
    #pragma unroll
    for (int u = 0; u < 12; u++) w[u] = wp[u];
    if (t < NC) s_bq[t] = bh[g * NC + t];

    const int start = g_off[g], end = g_off[g + 1];

    uint32_t nxt = 0;
    if (start < end && t < 96) nxt = g_feat16[(size_t)g_order[start] * 96 + t];
    __syncthreads();

    for (int s = start; s < end; s++) {
        if (t < 96) {
            const __half2 hh = *(const __half2*)&nxt;
            const float2 fv = __half22float2(hh);
            s_feat[2 * t]     = fv.x;
            s_feat[2 * t + 1] = fv.y;
        }
        __syncthreads();
        if (s + 1 < end && t < 96)
            nxt = g_feat16[(size_t)g_order[s + 1] * 96 + t];
        float p = 0.f;
        const float* fp2 = s_feat + j * 12;
        #pragma unroll
        for (int u = 0; u < 12; u++) p += w[u] * fp2[u];
        s_part[t] = p;
        __syncthreads();
        if (t < NC) {
            float sum = s_bq[t];
            #pragma unroll
            for (int jj = 0; jj < 16; jj++) sum += s_part[t + 16 * jj];
            out[(size_t)g_order[s] * NC + t] = sum;
        }
        __syncthreads();
    }
}

// ---------------- launch ----------------
extern "C" void kernel_launch(void* const* d_in, const int* in_sizes, int n_in,
                              void* d_out, int out_size) {
    const float* x   = (const float*)d_in[0];
    const int*   qid = (const int*)d_in[1];
    const int*   cor = (const int*)d_in[2];
    const float* W1  = (const float*)d_in[3];
    const float* b1  = (const float*)d_in[4];
    const float* W2  = (const float*)d_in[5];
    const float* b2  = (const float*)d_in[6];
    const float* Wh  = (const float*)d_in[7];
    const float* bh  = (const float*)d_in[8];
    float* out = (float*)d_out;

    cudaFuncSetAttribute(trunk_kernel, cudaFuncAttributeMaxDynamicSharedMemorySize, FUSED_SMEM);

    // order chosen so trunk_kernel is the 4th launch (profiler window)
    zero_kernel<<<(NHEADS + 255) / 256, 256>>>();
    hist_kernel<<<(B_TOTAL + 255) / 256, 256>>>(qid, cor);
    prep_kernel<<<(D_H * KPAD1 + D_H * D_H + 255) / 256, 256>>>(W1, W2);
    trunk_kernel<<<B_TOTAL / 64, 256, FUSED_SMEM>>>(x, b1, b2);
    scan_kernel<<<1, 1024>>>();
    scatter_kernel<<<(B_TOTAL + 255) / 256, 256>>>(qid, cor);
    heads_kernel<<<NHEADS, 256>>>(Wh, bh, out);
}

// round 9
// speedup vs baseline: 3.1216x; 1.4335x over previous
#include <cuda_runtime.h>
#include <cuda_fp16.h>
#include <cstdint>
#include <cstddef>

// ---------------- problem constants ----------------
#define B_TOTAL 131072
#define D_INPUT 385
#define D_H     192
#define NQ      1000
#define NHEADS  2000
#define NC      16

#define KPAD1   416            // 13 chunks of 32
#define NCH1    13
#define NCH2    6
#define PA      40             // A/H smem pitch (halves); 80B row stride -> LDSM conflict-free
#define PB      40             // B smem pitch (halves)

// ---------------- scratch (device globals: allocation-free) ----------------
__device__ uint32_t g_feat16[(size_t)B_TOTAL * 96];  // trunk output fp16, 50 MB
__device__ __half   g_W1h[D_H * KPAD1];              // W1^T fp16 [n][KPAD1], zero-padded
__device__ __half   g_W2h[D_H * D_H];                // W2^T fp16 [n][192]
__device__ int      g_cnt[NHEADS];
__device__ int      g_off[NHEADS + 1];
__device__ int      g_cur[NHEADS];
__device__ int      g_order[B_TOTAL];

// ---------------- PTX helpers ----------------
#define CP16(dst, src) \
    asm volatile("cp.async.cg.shared.global [%0], [%1], 16;" \
                 :: "r"(dst), "l"(__cvta_generic_to_global((const void*)(src))))
#define CP_COMMIT() asm volatile("cp.async.commit_group;" ::: "memory")
#define CP_WAIT0()  asm volatile("cp.async.wait_group 0;" ::: "memory")

__device__ __forceinline__ void ldsm4(uint32_t r[4], uint32_t addr) {
    asm volatile("ldmatrix.sync.aligned.m8n8.x4.shared.b16 {%0,%1,%2,%3}, [%4];"
        : "=r"(r[0]), "=r"(r[1]), "=r"(r[2]), "=r"(r[3]) : "r"(addr));
}

__device__ __forceinline__ void mma16(float c[4], uint32_t a0, uint32_t a1,
                                      uint32_t a2, uint32_t a3, uint32_t b0, uint32_t b1) {
    asm volatile(
        "mma.sync.aligned.m16n8k16.row.col.f32.f16.f16.f32 "
        "{%0,%1,%2,%3}, {%4,%5,%6,%7}, {%8,%9}, {%0,%1,%2,%3};\n"
        : "+f"(c[0]), "+f"(c[1]), "+f"(c[2]), "+f"(c[3])
        : "r"(a0), "r"(a1), "r"(a2), "r"(a3), "r"(b0), "r"(b1));
}

// ---------------- prep: W1/W2 -> transposed fp16 (plain layout) ----------------
__global__ void prep_kernel(const float* __restrict__ W1, const float* __restrict__ W2) {
    int i = blockIdx.x * blockDim.x + threadIdx.x;
    const int T1 = D_H * KPAD1;
    if (i < T1) {
        int n = i / KPAD1, k = i - n * KPAD1;
        float v = (k < D_INPUT) ? W1[(size_t)k * D_H + n] : 0.f;
        g_W1h[i] = __float2half_rn(v);
    } else {
        int j = i - T1;
        if (j < D_H * D_H) {
            int n = j / D_H, k = j - n * D_H;
            g_W2h[j] = __float2half_rn(W2[(size_t)k * D_H + n]);
        }
    }
}

// ---------------- fused trunk ----------------
// 256 threads = 8 warps: wm = wid&1 (M, 32 rows), wn = wid>>1 (N, 48 cols).
// CTA tile 64x192, 2 CTAs/SM. Fragments via ldmatrix.x4, fp16 m16n8k16.
struct Frag { float c[2][6][4]; };

__device__ __forceinline__ void compute_chunk(uint32_t abase, uint32_t bbase,
                                              Frag& f, int wm, int wn, int lane)
{
    const int arow = ((lane >> 3) & 1) * 8 + (lane & 7);
    const int ak   = (lane >> 4) * 8;
    const int bn   = ((lane >> 4) & 1) * 8 + (lane & 7);
    const int bk   = ((lane >> 3) & 1) * 8;
    #pragma unroll
    for (int g = 0; g < 2; g++) {
        uint32_t a[2][4], b[3][4];
        #pragma unroll
        for (int mt = 0; mt < 2; mt++)
            ldsm4(a[mt], abase + (uint32_t)(((wm * 32 + mt * 16 + arow) * PA + g * 16 + ak) * 2));
        #pragma unroll
        for (int p = 0; p < 3; p++)
            ldsm4(b[p], bbase + (uint32_t)(((wn * 48 + p * 16 + bn) * PB + g * 16 + bk) * 2));
        #pragma unroll
        for (int mt = 0; mt < 2; mt++)
            #pragma unroll
            for (int nt = 0; nt < 6; nt++)
                mma16(f.c[mt][nt], a[mt][0], a[mt][1], a[mt][2], a[mt][3],
                      b[nt >> 1][(nt & 1) * 2], b[nt >> 1][(nt & 1) * 2 + 1]);
    }
}

// smem layout (bytes): A0 @0 (5120), A1 @5120, B0 @10240 (15360), B1 @25600,
//                      H blocks @40960 (6 x 5120)
#define SM_A(b)  ((b) * 5120)
#define SM_B(b)  (10240 + (b) * 15360)
#define SM_H(c)  (40960 + (c) * 5120)
#define FUSED_SMEM 71680

__global__ void __launch_bounds__(256, 2) trunk_kernel(
    const float* __restrict__ x, const float* __restrict__ b1, const float* __restrict__ b2)
{
    extern __shared__ char sm[];
    const uint32_t sb = (uint32_t)__cvta_generic_to_shared(sm);
    const int tid  = threadIdx.x;
    const int lane = tid & 31;
    const int wid  = tid >> 5;
    const int wm   = wid & 1, wn = wid >> 1;
    const int row0 = blockIdx.x * 64;
    const int myk  = tid & 31;
    const int rb   = tid >> 5;

    Frag f;
    #pragma unroll
    for (int mt = 0; mt < 2; mt++)
        #pragma unroll
        for (int nt = 0; nt < 6; nt++)
            #pragma unroll
            for (int q = 0; q < 4; q++) f.c[mt][nt][q] = 0.f;

    // ================= phase 1: h = relu(x @ W1 + b1) =================
    {
        #pragma unroll
        for (int t = 0; t < 3; t++) {
            const int i = tid + t * 256;
            CP16(sb + SM_B(0) + (uint32_t)(((i >> 2) * PB + (i & 3) * 8) * 2),
                 g_W1h + (i >> 2) * KPAD1 + (i & 3) * 8);
        }
        CP_COMMIT();
    }
    {
        __half* Ah = (__half*)(sm + SM_A(0));
        const bool kv = (myk < D_INPUT);
        #pragma unroll
        for (int t = 0; t < 8; t++) {
            const int r = rb + t * 8;
            float v = kv ? __ldg(&x[(size_t)(row0 + r) * D_INPUT + myk]) : 0.f;
            Ah[r * PA + myk] = __float2half_rn(v);
        }
    }
    CP_WAIT0();
    __syncthreads();

    for (int c = 0; c < NCH1; c++) {
        const int nx = c + 1;
        float xa[8];
        if (nx < NCH1) {
            const uint32_t bdst = sb + SM_B(nx & 1);
            #pragma unroll
            for (int t = 0; t < 3; t++) {
                const int i = tid + t * 256;
                CP16(bdst + (uint32_t)(((i >> 2) * PB + (i & 3) * 8) * 2),
                     g_W1h + (i >> 2) * KPAD1 + nx * 32 + (i & 3) * 8);
            }
            CP_COMMIT();
            const int k = nx * 32 + myk;
            const bool kv = (k < D_INPUT);
            #pragma unroll
            for (int t = 0; t < 8; t++) {
                const int r = rb + t * 8;
                xa[t] = kv ? __ldg(&x[(size_t)(row0 + r) * D_INPUT + k]) : 0.f;
            }
        }
        compute_chunk(sb + SM_A(c & 1), sb + SM_B(c & 1), f, wm, wn, lane);
        if (nx < NCH1) {
            __half* Ad = (__half*)(sm + SM_A(nx & 1));
            #pragma unroll
            for (int t = 0; t < 8; t++) {
                const int r = rb + t * 8;
                Ad[r * PA + myk] = __float2half_rn(xa[t]);
            }
            CP_WAIT0();
        }
        __syncthreads();
    }

    // ---- prefetch W2 chunk 0 into B0 (overlaps epilogue 1) ----
    {
        #pragma unroll
        for (int t = 0; t < 3; t++) {
            const int i = tid + t * 256;
            CP16(sb + SM_B(0) + (uint32_t)(((i >> 2) * PB + (i & 3) * 8) * 2),
                 g_W2h + (i >> 2) * D_H + (i & 3) * 8);
        }
        CP_COMMIT();
    }

    // ---- epilogue 1: H blocks = fp16(relu(c + b1)) in smem ----
    #pragma unroll
    for (int mt = 0; mt < 2; mt++) {
        const int r = wm * 32 + mt * 16 + (lane >> 2);
        #pragma unroll
        for (int nt = 0; nt < 6; nt++) {
            const int n = wn * 48 + nt * 8 + 2 * (lane & 3);
            const float bb0 = __ldg(&b1[n]), bb1 = __ldg(&b1[n + 1]);
            __half2 v0 = __floats2half2_rn(fmaxf(f.c[mt][nt][0] + bb0, 0.f),
                                           fmaxf(f.c[mt][nt][1] + bb1, 0.f));
            __half2 v1 = __floats2half2_rn(fmaxf(f.c[mt][nt][2] + bb0, 0.f),
                                           fmaxf(f.c[mt][nt][3] + bb1, 0.f));
            const uint32_t off = (uint32_t)(SM_H(n >> 5) + (r * PA + (n & 31)) * 2);
            *(uint32_t*)(sm + off)       = *(uint32_t*)&v0;
            *(uint32_t*)(sm + off + PA * 16) = *(uint32_t*)&v1;
        }
    }

    #pragma unroll
    for (int mt = 0; mt < 2; mt++)
        #pragma unroll
        for (int nt = 0; nt < 6; nt++)
            #pragma unroll
            for (int q = 0; q < 4; q++) f.c[mt][nt][q] = 0.f;

    CP_WAIT0();
    __syncthreads();

    // ================= phase 2: feat = relu(H @ W2 + b2) =================
    for (int c = 0; c < NCH2; c++) {
        const int nx = c + 1;
        if (nx < NCH2) {
            const uint32_t bdst = sb + SM_B(nx & 1);
            #pragma unroll
            for (int t = 0; t < 3; t++) {
                const int i = tid + t * 256;
                CP16(bdst + (uint32_t)(((i >> 2) * PB + (i & 3) * 8) * 2),
                     g_W2h + (i >> 2) * D_H + nx * 32 + (i & 3) * 8);
            }
            CP_COMMIT();
        }
        compute_chunk(sb + SM_H(c), sb + SM_B(c & 1), f, wm, wn, lane);
        if (nx < NCH2) CP_WAIT0();
        __syncthreads();
    }

    // ---- epilogue 2: g_feat16 = fp16(relu(c + b2)) ----
    #pragma unroll
    for (int mt = 0; mt < 2; mt++) {
        const int r = row0 + wm * 32 + mt * 16 + (lane >> 2);
        #pragma unroll
        for (int nt = 0; nt < 6; nt++) {
            const int n = wn * 48 + nt * 8 + 2 * (lane & 3);
            const float bb0 = __ldg(&b2[n]), bb1 = __ldg(&b2[n + 1]);
            __half2 v0 = __floats2half2_rn(fmaxf(f.c[mt][nt][0] + bb0, 0.f),
                                           fmaxf(f.c[mt][nt][1] + bb1, 0.f));
            __half2 v1 = __floats2half2_rn(fmaxf(f.c[mt][nt][2] + bb0, 0.f),
                                           fmaxf(f.c[mt][nt][3] + bb1, 0.f));
            g_feat16[(size_t)r * 96 + (n >> 1)]       = *(uint32_t*)&v0;
            g_feat16[(size_t)(r + 8) * 96 + (n >> 1)] = *(uint32_t*)&v1;
        }
    }
}

// ---------------- binning: histogram -> scan -> scatter ----------------
__global__ void zero_kernel() {
    int i = blockIdx.x * blockDim.x + threadIdx.x;
    if (i < NHEADS) g_cnt[i] = 0;
}

__global__ void hist_kernel(const int* __restrict__ qid, const int* __restrict__ cor) {
    int b = blockIdx.x * blockDim.x + threadIdx.x;
    if (b < B_TOTAL) atomicAdd(&g_cnt[qid[b] + cor[b] * NQ], 1);
}

__global__ void scan_kernel() {
    __shared__ int s[2048];
    const int t = threadIdx.x;
    s[t]        = (t < NHEADS) ? g_cnt[t] : 0;
    s[t + 1024] = (t + 1024 < NHEADS) ? g_cnt[t + 1024] : 0;
    __syncthreads();
    for (int d = 1; d < 2048; d <<= 1) {
        int v0 = s[t], v1 = s[t + 1024];
        int a0 = (t >= d) ? s[t - d] : 0;
        int a1 = (t + 1024 >= d) ? s[t + 1024 - d] : 0;
        __syncthreads();
        s[t] = v0 + a0;
        s[t + 1024] = v1 + a1;
        __syncthreads();
    }
    if (t < NHEADS)          { int e = (t == 0) ? 0 : s[t - 1]; g_off[t] = e; g_cur[t] = e; }
    if (t + 1024 < NHEADS)   { int e = s[t + 1023];             g_off[t + 1024] = e; g_cur[t + 1024] = e; }
    if (t == 0) g_off[NHEADS] = s[NHEADS - 1];
}

__global__ void scatter_kernel(const int* __restrict__ qid, const int* __restrict__ cor) {
    int b = blockIdx.x * blockDim.x + threadIdx.x;
    if (b < B_TOTAL) {
        int h = qid[b] + cor[b] * NQ;
        int p = atomicAdd(&g_cur[h], 1);
        g_order[p] = b;
    }
}

// ---------------- routed heads: one WARP per head group, tensor-core GEMM ----------------
// Per 16-sample tile: gather feat rows via cp.async into per-warp smem, ldmatrix.x4,
// 24 HMMA (M16 x N16 x K192), masked scattered stores. No CTA barriers.
#define HROW_B   400           // smem row stride bytes (200 halves); banks 4r -> conflict-free
#define H_WARP_B 6400          // 16 rows * 400 B
#define HEADS_SMEM (8 * H_WARP_B)

__global__ void __launch_bounds__(256, 2) heads_kernel(
    const float* __restrict__ Wh, const float* __restrict__ bh, float* __restrict__ out)
{
    extern __shared__ char sm[];
    const int tid  = threadIdx.x;
    const int lane = tid & 31;
    const int wid  = tid >> 5;
    const int g    = blockIdx.x * 8 + wid;           // 250*8 = 2000 exactly
    const uint32_t wbase = (uint32_t)__cvta_generic_to_shared(sm) + (uint32_t)(wid * H_WARP_B);

    const int start = g_off[g], end = g_off[g + 1];
    if (start >= end) return;                        // warp-uniform

    // ---- B fragments (weights, fp16) in registers: bw[kk][p][2] ----
    uint32_t bw[48];
    {
        const int n_lo = lane >> 2, q2 = 2 * (lane & 3);
        #pragma unroll
        for (int kk = 0; kk < 12; kk++) {
            #pragma unroll
            for (int p = 0; p < 2; p++) {
                const float* src = Wh + ((size_t)g * NC + p * 8 + n_lo) * D_H + kk * 16 + q2;
                const float2 lo = *(const float2*)src;
                const float2 hi = *(const float2*)(src + 8);
                const __half2 l2 = __floats2half2_rn(lo.x, lo.y);
                const __half2 h2 = __floats2half2_rn(hi.x, hi.y);
                bw[kk * 4 + p * 2]     = *(const uint32_t*)&l2;
                bw[kk * 4 + p * 2 + 1] = *(const uint32_t*)&h2;
            }
        }
    }
    // ---- bias ----
    float bb[2][2];
    {
        const int col = 2 * (lane & 3);
        bb[0][0] = __ldg(&bh[g * NC + col]);
        bb[0][1] = __ldg(&bh[g * NC + col + 1]);
        bb[1][0] = __ldg(&bh[g * NC + 8 + col]);
        bb[1][1] = __ldg(&bh[g * NC + 8 + col + 1]);
    }

    const int myrow = lane & 15;          // gather row (2 lanes per row)
    const int seg0  = (lane >> 4) * 12;   // 12 x 16B segments per half-lane
    const int arow  = ((lane >> 3) & 1) * 8 + (lane & 7);
    const int ak2   = ((lane >> 4) * 8) * 2;   // byte offset 0 or 16
    const int r0    = lane >> 2, col = 2 * (lane & 3);

    for (int s0 = start; s0 < end; s0 += 16) {
        // ---- gather 16 feat rows (dup-clamped tail) ----
        {
            const int sIdx = s0 + myrow;
            const int sC = (sIdx < end) ? sIdx : (end - 1);
            const char* src = (const char*)(g_feat16 + (size_t)g_order[sC] * 96);
            const uint32_t dst = wbase + (uint32_t)(myrow * HROW_B);
            #pragma unroll
            for (int t = 0; t < 12; t++) {
                const int j = seg0 + t;
                CP16(dst + (uint32_t)(j * 16), src + j * 16);
            }
            CP_COMMIT();
            CP_WAIT0();
            __syncwarp();
        }

        float acc[2][4];
        #pragma unroll
        for (int p = 0; p < 2; p++)
            #pragma unroll
            for (int q = 0; q < 4; q++) acc[p][q] = 0.f;

        #pragma unroll
        for (int kk = 0; kk < 12; kk++) {
            uint32_t a[4];
            ldsm4(a, wbase + (uint32_t)(arow * HROW_B + kk * 32) + (uint32_t)ak2);
            mma16(acc[0], a[0], a[1], a[2], a[3], bw[kk * 4],     bw[kk * 4 + 1]);
            mma16(acc[1], a[0], a[1], a[2], a[3], bw[kk * 4 + 2], bw[kk * 4 + 3]);
        }
        __syncwarp();   // all lanes done reading smem before next gather overwrites

        // ---- epilogue: masked scattered stores ----
        const int s_a = s0 + r0, s_b = s0 + r0 + 8;
        if (s_a < end) {
            float* o = out + (size_t)g_order[s_a] * NC;
            float2 v0 = { acc[0][0] + bb[0][0], acc[0][1] + bb[0][1] };
            float2 v1 = { acc[1][0] + bb[1][0], acc[1][1] + bb[1][1] };
            *(float2*)(o + col)     = v0;
            *(float2*)(o + 8 + col) = v1;
        }
        if (s_b < end) {
            float* o = out + (size_t)g_order[s_b] * NC;
            float2 v0 = { acc[0][2] + bb[0][0], acc[0][3] + bb[0][1] };
            float2 v1 = { acc[1][2] + bb[1][0], acc[1][3] + bb[1][1] };
            *(float2*)(o + col)     = v0;
            *(float2*)(o + 8 + col) = v1;
        }
    }
}

// ---------------- launch ----------------
extern "C" void kernel_launch(void* const* d_in, const int* in_sizes, int n_in,
                              void* d_out, int out_size) {
    const float* x   = (const float*)d_in[0];
    const int*   qid = (const int*)d_in[1];
    const int*   cor = (const int*)d_in[2];
    const float* W1  = (const float*)d_in[3];
    const float* b1  = (const float*)d_in[4];
    const float* W2  = (const float*)d_in[5];
    const float* b2  = (const float*)d_in[6];
    const float* Wh  = (const float*)d_in[7];
    const float* bh  = (const float*)d_in[8];
    float* out = (float*)d_out;

    cudaFuncSetAttribute(trunk_kernel, cudaFuncAttributeMaxDynamicSharedMemorySize, FUSED_SMEM);
    cudaFuncSetAttribute(heads_kernel, cudaFuncAttributeMaxDynamicSharedMemorySize, HEADS_SMEM);

    // order chosen so trunk_kernel is the 4th launch (profiler window)
    zero_kernel<<<(NHEADS + 255) / 256, 256>>>();
    hist_kernel<<<(B_TOTAL + 255) / 256, 256>>>(qid, cor);
    prep_kernel<<<(D_H * KPAD1 + D_H * D_H + 255) / 256, 256>>>(W1, W2);
    trunk_kernel<<<B_TOTAL / 64, 256, FUSED_SMEM>>>(x, b1, b2);
    scan_kernel<<<1, 1024>>>();
    scatter_kernel<<<(B_TOTAL + 255) / 256, 256>>>(qid, cor);
    heads_kernel<<<NHEADS / 8, 256, HEADS_SMEM>>>(Wh, bh, out);
}

// round 10
// speedup vs baseline: 3.1867x; 1.0209x over previous
#include <cuda_runtime.h>
#include <cuda_fp16.h>
#include <cstdint>
#include <cstddef>

// ---------------- problem constants ----------------
#define B_TOTAL 131072
#define D_INPUT 385
#define D_H     192
#define NQ      1000
#define NHEADS  2000
#define NC      16

#define KPAD1   448            // 7 chunks of 64
#define NCH1    7
#define NCH2    3
#define PA      72             // smem pitch (halves); 144B row stride -> LDSM banks 4r, conflict-free

// ---------------- scratch (device globals: allocation-free) ----------------
__device__ uint32_t g_feat16[(size_t)B_TOTAL * 96];  // trunk output fp16, 50 MB
__device__ __half   g_W1h[D_H * KPAD1];              // W1^T fp16 [n][448], zero-padded
__device__ __half   g_W2h[D_H * D_H];                // W2^T fp16 [n][192]
__device__ int      g_cnt[NHEADS];
__device__ int      g_off[NHEADS + 1];
__device__ int      g_cur[NHEADS];
__device__ int      g_order[B_TOTAL];

// ---------------- PTX helpers ----------------
#define CP16(dst, src) \
    asm volatile("cp.async.cg.shared.global [%0], [%1], 16;" \
                 :: "r"(dst), "l"(__cvta_generic_to_global((const void*)(src))))
#define CP_COMMIT() asm volatile("cp.async.commit_group;" ::: "memory")
#define CP_WAIT0()  asm volatile("cp.async.wait_group 0;" ::: "memory")

__device__ __forceinline__ void ldsm4(uint32_t r[4], uint32_t addr) {
    asm volatile("ldmatrix.sync.aligned.m8n8.x4.shared.b16 {%0,%1,%2,%3}, [%4];"
        : "=r"(r[0]), "=r"(r[1]), "=r"(r[2]), "=r"(r[3]) : "r"(addr));
}

__device__ __forceinline__ void mma16(float c[4], uint32_t a0, uint32_t a1,
                                      uint32_t a2, uint32_t a3, uint32_t b0, uint32_t b1) {
    asm volatile(
        "mma.sync.aligned.m16n8k16.row.col.f32.f16.f16.f32 "
        "{%0,%1,%2,%3}, {%4,%5,%6,%7}, {%8,%9}, {%0,%1,%2,%3};\n"
        : "+f"(c[0]), "+f"(c[1]), "+f"(c[2]), "+f"(c[3])
        : "r"(a0), "r"(a1), "r"(a2), "r"(a3), "r"(b0), "r"(b1));
}

// ---------------- prep: W1/W2 -> transposed fp16 (plain layout) ----------------
__global__ void prep_kernel(const float* __restrict__ W1, const float* __restrict__ W2) {
    int i = blockIdx.x * blockDim.x + threadIdx.x;
    const int T1 = D_H * KPAD1;
    if (i < T1) {
        int n = i / KPAD1, k = i - n * KPAD1;
        float v = (k < D_INPUT) ? W1[(size_t)k * D_H + n] : 0.f;
        g_W1h[i] = __float2half_rn(v);
    } else {
        int j = i - T1;
        if (j < D_H * D_H) {
            int n = j / D_H, k = j - n * D_H;
            g_W2h[j] = __float2half_rn(W2[(size_t)k * D_H + n]);
        }
    }
}

// ---------------- fused trunk, K64 chunks ----------------
// 256 threads = 8 warps: wm = wid&1 (M, 32 rows), wn = wid>>1 (N, 48 cols).
// CTA tile 64x192, 2 CTAs/SM. ldmatrix.x4 + fp16 m16n8k16. 10 sync walls total.
struct Frag { float c[2][6][4]; };

// compute g-steps [g0, g1] of a K64 chunk (g in 0..3, each = k16)
__device__ __forceinline__ void compute_part(uint32_t abase, uint32_t bbase,
                                             Frag& f, int wm, int wn, int lane,
                                             int g0, int g1)
{
    const int arow = ((lane >> 3) & 1) * 8 + (lane & 7);
    const int ak   = (lane >> 4) * 8;
    const int bn   = ((lane >> 4) & 1) * 8 + (lane & 7);
    const int bk   = ((lane >> 3) & 1) * 8;
    #pragma unroll
    for (int g = g0; g <= g1; g++) {
        uint32_t a[2][4], b[3][4];
        #pragma unroll
        for (int mt = 0; mt < 2; mt++)
            ldsm4(a[mt], abase + (uint32_t)(((wm * 32 + mt * 16 + arow) * PA + g * 16 + ak) * 2));
        #pragma unroll
        for (int p = 0; p < 3; p++)
            ldsm4(b[p], bbase + (uint32_t)(((wn * 48 + p * 16 + bn) * PA + g * 16 + bk) * 2));
        #pragma unroll
        for (int mt = 0; mt < 2; mt++)
            #pragma unroll
            for (int nt = 0; nt < 6; nt++)
                mma16(f.c[mt][nt], a[mt][0], a[mt][1], a[mt][2], a[mt][3],
                      b[nt >> 1][(nt & 1) * 2], b[nt >> 1][(nt & 1) * 2 + 1]);
    }
}

// smem layout (bytes): A0 @0 (9216), A1 @9216, B0 @18432 (27648), B1 @46080,
//                      H blocks @73728 (3 x 9216) -> total 101376 (2 CTAs/SM)
#define SM_A(b)  ((b) * 9216)
#define SM_B(b)  (18432 + (b) * 27648)
#define SM_H(c)  (73728 + (c) * 9216)
#define FUSED_SMEM 101376

__global__ void __launch_bounds__(256, 2) trunk_kernel(
    const float* __restrict__ x, const float* __restrict__ b1, const float* __restrict__ b2)
{
    extern __shared__ char sm[];
    const uint32_t sb = (uint32_t)__cvta_generic_to_shared(sm);
    const int tid  = threadIdx.x;
    const int lane = tid & 31;
    const int wid  = tid >> 5;
    const int wm   = wid & 1, wn = wid >> 1;
    const int row0 = blockIdx.x * 64;
    const int myk   = tid & 63;          // k within chunk for A loads
    const int rbase = tid >> 6;          // row base (0..3), rows rbase + 4t

    Frag f;
    #pragma unroll
    for (int mt = 0; mt < 2; mt++)
        #pragma unroll
        for (int nt = 0; nt < 6; nt++)
            #pragma unroll
            for (int q = 0; q < 4; q++) f.c[mt][nt][q] = 0.f;

    // ================= phase 1: h = relu(x @ W1 + b1) =================
    // prologue: B0 (192x64 fp16 = 1536 segs) via cp.async, A0 via LDG+convert+STS
    {
        #pragma unroll
        for (int t = 0; t < 6; t++) {
            const int i = tid + t * 256, n = i >> 3, j = i & 7;
            CP16(sb + SM_B(0) + (uint32_t)(n * 144 + j * 16),
                 g_W1h + n * KPAD1 + j * 8);
        }
        CP_COMMIT();
    }
    {
        __half* Ah = (__half*)(sm + SM_A(0));
        const bool kv = (myk < D_INPUT);
        #pragma unroll
        for (int t = 0; t < 16; t++) {
            const int r = rbase + t * 4;
            float v = kv ? __ldg(&x[(size_t)(row0 + r) * D_INPUT + myk]) : 0.f;
            Ah[r * PA + myk] = __float2half_rn(v);
        }
    }
    CP_WAIT0();
    __syncthreads();

    for (int c = 0; c < NCH1; c++) {
        const int nx = c + 1;
        float xa[8];
        const int k = nx * 64 + myk;
        const bool kv = (k < D_INPUT);
        if (nx < NCH1) {
            const uint32_t bdst = sb + SM_B(nx & 1);
            #pragma unroll
            for (int t = 0; t < 6; t++) {
                const int i = tid + t * 256, n = i >> 3, j = i & 7;
                CP16(bdst + (uint32_t)(n * 144 + j * 16),
                     g_W1h + n * KPAD1 + nx * 64 + j * 8);
            }
            CP_COMMIT();
            #pragma unroll
            for (int t = 0; t < 8; t++) {
                const int r = rbase + t * 4;
                xa[t] = kv ? __ldg(&x[(size_t)(row0 + r) * D_INPUT + k]) : 0.f;
            }
        }
        compute_part(sb + SM_A(c & 1), sb + SM_B(c & 1), f, wm, wn, lane, 0, 1);
        if (nx < NCH1) {
            __half* Ad = (__half*)(sm + SM_A(nx & 1));
            #pragma unroll
            for (int t = 0; t < 8; t++) {
                const int r = rbase + t * 4;
                Ad[r * PA + myk] = __float2half_rn(xa[t]);
            }
            #pragma unroll
            for (int t = 0; t < 8; t++) {
                const int r = rbase + (t + 8) * 4;
                xa[t] = kv ? __ldg(&x[(size_t)(row0 + r) * D_INPUT + k]) : 0.f;
            }
        }
        compute_part(sb + SM_A(c & 1), sb + SM_B(c & 1), f, wm, wn, lane, 2, 3);
        if (nx < NCH1) {
            __half* Ad = (__half*)(sm + SM_A(nx & 1));
            #pragma unroll
            for (int t = 0; t < 8; t++) {
                const int r = rbase + (t + 8) * 4;
                Ad[r * PA + myk] = __float2half_rn(xa[t]);
            }
            CP_WAIT0();
        }
        __syncthreads();
    }

    // ---- prefetch W2 chunk 0 into B0 (overlaps epilogue 1; B0 free after last sync) ----
    {
        #pragma unroll
        for (int t = 0; t < 6; t++) {
            const int i = tid + t * 256, n = i >> 3, j = i & 7;
            CP16(sb + SM_B(0) + (uint32_t)(n * 144 + j * 16),
                 g_W2h + n * D_H + j * 8);
        }
        CP_COMMIT();
    }

    // ---- epilogue 1: H blocks = fp16(relu(c + b1)) in smem ----
    #pragma unroll
    for (int mt = 0; mt < 2; mt++) {
        const int r = wm * 32 + mt * 16 + (lane >> 2);
        #pragma unroll
        for (int nt = 0; nt < 6; nt++) {
            const int n = wn * 48 + nt * 8 + 2 * (lane & 3);
            const float bb0 = __ldg(&b1[n]), bb1 = __ldg(&b1[n + 1]);
            __half2 v0 = __floats2half2_rn(fmaxf(f.c[mt][nt][0] + bb0, 0.f),
                                           fmaxf(f.c[mt][nt][1] + bb1, 0.f));
            __half2 v1 = __floats2half2_rn(fmaxf(f.c[mt][nt][2] + bb0, 0.f),
                                           fmaxf(f.c[mt][nt][3] + bb1, 0.f));
            const uint32_t off = (uint32_t)(SM_H(n >> 6) + (r * PA + (n & 63)) * 2);
            *(uint32_t*)(sm + off)            = *(uint32_t*)&v0;
            *(uint32_t*)(sm + off + PA * 16)  = *(uint32_t*)&v1;   // +8 rows
        }
    }

    #pragma unroll
    for (int mt = 0; mt < 2; mt++)
        #pragma unroll
        for (int nt = 0; nt < 6; nt++)
            #pragma unroll
            for (int q = 0; q < 4; q++) f.c[mt][nt][q] = 0.f;

    CP_WAIT0();
    __syncthreads();

    // ================= phase 2: feat = relu(H @ W2 + b2) =================
    for (int c = 0; c < NCH2; c++) {
        const int nx = c + 1;
        if (nx < NCH2) {
            const uint32_t bdst = sb + SM_B(nx & 1);
            #pragma unroll
            for (int t = 0; t < 6; t++) {
                const int i = tid + t * 256, n = i >> 3, j = i & 7;
                CP16(bdst + (uint32_t)(n * 144 + j * 16),
                     g_W2h + n * D_H + nx * 64 + j * 8);
            }
            CP_COMMIT();
        }
        compute_part(sb + SM_H(c), sb + SM_B(c & 1), f, wm, wn, lane, 0, 3);
        if (nx < NCH2) CP_WAIT0();
        __syncthreads();
    }

    // ---- epilogue 2: g_feat16 = fp16(relu(c + b2)) ----
    #pragma unroll
    for (int mt = 0; mt < 2; mt++) {
        const int r = row0 + wm * 32 + mt * 16 + (lane >> 2);
        #pragma unroll
        for (int nt = 0; nt < 6; nt++) {
            const int n = wn * 48 + nt * 8 + 2 * (lane & 3);
            const float bb0 = __ldg(&b2[n]), bb1 = __ldg(&b2[n + 1]);
            __half2 v0 = __floats2half2_rn(fmaxf(f.c[mt][nt][0] + bb0, 0.f),
                                           fmaxf(f.c[mt][nt][1] + bb1, 0.f));
            __half2 v1 = __floats2half2_rn(fmaxf(f.c[mt][nt][2] + bb0, 0.f),
                                           fmaxf(f.c[mt][nt][3] + bb1, 0.f));
            g_feat16[(size_t)r * 96 + (n >> 1)]       = *(uint32_t*)&v0;
            g_feat16[(size_t)(r + 8) * 96 + (n >> 1)] = *(uint32_t*)&v1;
        }
    }
}

// ---------------- binning: histogram -> scan -> scatter ----------------
__global__ void zero_kernel() {
    int i = blockIdx.x * blockDim.x + threadIdx.x;
    if (i < NHEADS) g_cnt[i] = 0;
}

__global__ void hist_kernel(const int* __restrict__ qid, const int* __restrict__ cor) {
    int b = blockIdx.x * blockDim.x + threadIdx.x;
    if (b < B_TOTAL) atomicAdd(&g_cnt[qid[b] + cor[b] * NQ], 1);
}

__global__ void scan_kernel() {
    __shared__ int s[2048];
    const int t = threadIdx.x;
    s[t]        = (t < NHEADS) ? g_cnt[t] : 0;
    s[t + 1024] = (t + 1024 < NHEADS) ? g_cnt[t + 1024] : 0;
    __syncthreads();
    for (int d = 1; d < 2048; d <<= 1) {
        int v0 = s[t], v1 = s[t + 1024];
        int a0 = (t >= d) ? s[t - d] : 0;
        int a1 = (t + 1024 >= d) ? s[t + 1024 - d] : 0;
        __syncthreads();
        s[t] = v0 + a0;
        s[t + 1024] = v1 + a1;
        __syncthreads();
    }
    if (t < NHEADS)          { int e = (t == 0) ? 0 : s[t - 1]; g_off[t] = e; g_cur[t] = e; }
    if (t + 1024 < NHEADS)   { int e = s[t + 1023];             g_off[t + 1024] = e; g_cur[t + 1024] = e; }
    if (t == 0) g_off[NHEADS] = s[NHEADS - 1];
}

__global__ void scatter_kernel(const int* __restrict__ qid, const int* __restrict__ cor) {
    int b = blockIdx.x * blockDim.x + threadIdx.x;
    if (b < B_TOTAL) {
        int h = qid[b] + cor[b] * NQ;
        int p = atomicAdd(&g_cur[h], 1);
        g_order[p] = b;
    }
}

// ---------------- routed heads: one WARP per head group, tensor-core GEMM ----------------
#define HROW_B   400
#define H_WARP_B 6400
#define HEADS_SMEM (8 * H_WARP_B)

__global__ void __launch_bounds__(256, 2) heads_kernel(
    const float* __restrict__ Wh, const float* __restrict__ bh, float* __restrict__ out)
{
    extern __shared__ char sm[];
    const int tid  = threadIdx.x;
    const int lane = tid & 31;
    const int wid  = tid >> 5;
    const int g    = blockIdx.x * 8 + wid;
    const uint32_t wbase = (uint32_t)__cvta_generic_to_shared(sm) + (uint32_t)(wid * H_WARP_B);

    const int start = g_off[g], end = g_off[g + 1];
    if (start >= end) return;

    uint32_t bw[48];
    {
        const int n_lo = lane >> 2, q2 = 2 * (lane & 3);
        #pragma unroll
        for (int kk = 0; kk < 12; kk++) {
            #pragma unroll
            for (int p = 0; p < 2; p++) {
                const float* src = Wh + ((size_t)g * NC + p * 8 + n_lo) * D_H + kk * 16 + q2;
                const float2 lo = *(const float2*)src;
                const float2 hi = *(const float2*)(src + 8);
                const __half2 l2 = __floats2half2_rn(lo.x, lo.y);
                const __half2 h2 = __floats2half2_rn(hi.x, hi.y);
                bw[kk * 4 + p * 2]     = *(const uint32_t*)&l2;
                bw[kk * 4 + p * 2 + 1] = *(const uint32_t*)&h2;
            }
        }
    }
    float bb[2][2];
    {
        const int col = 2 * (lane & 3);
        bb[0][0] = __ldg(&bh[g * NC + col]);
        bb[0][1] = __ldg(&bh[g * NC + col + 1]);
        bb[1][0] = __ldg(&bh[g * NC + 8 + col]);
        bb[1][1] = __ldg(&bh[g * NC + 8 + col + 1]);
    }

    const int myrow = lane & 15;
    const int seg0  = (lane >> 4) * 12;
    const int arow  = ((lane >> 3) & 1) * 8 + (lane & 7);
    const int ak2   = ((lane >> 4) * 8) * 2;
    const int r0    = lane >> 2, col = 2 * (lane & 3);

    for (int s0 = start; s0 < end; s0 += 16) {
        {
            const int sIdx = s0 + myrow;
            const int sC = (sIdx < end) ? sIdx : (end - 1);
            const char* src = (const char*)(g_feat16 + (size_t)g_order[sC] * 96);
            const uint32_t dst = wbase + (uint32_t)(myrow * HROW_B);
            #pragma unroll
            for (int t = 0; t < 12; t++) {
                const int j = seg0 + t;
                CP16(dst + (uint32_t)(j * 16), src + j * 16);
            }
            CP_COMMIT();
            CP_WAIT0();
            __syncwarp();
        }

        float acc[2][4];
        #pragma unroll
        for (int p = 0; p < 2; p++)
            #pragma unroll
            for (int q = 0; q < 4; q++) acc[p][q] = 0.f;

        #pragma unroll
        for (int kk = 0; kk < 12; kk++) {
            uint32_t a[4];
            ldsm4(a, wbase + (uint32_t)(arow * HROW_B + kk * 32) + (uint32_t)ak2);
            mma16(acc[0], a[0], a[1], a[2], a[3], bw[kk * 4],     bw[kk * 4 + 1]);
            mma16(acc[1], a[0], a[1], a[2], a[3], bw[kk * 4 + 2], bw[kk * 4 + 3]);
        }
        __syncwarp();

        const int s_a = s0 + r0, s_b = s0 + r0 + 8;
        if (s_a < end) {
            float* o = out + (size_t)g_order[s_a] * NC;
            float2 v0 = { acc[0][0] + bb[0][0], acc[0][1] + bb[0][1] };
            float2 v1 = { acc[1][0] + bb[1][0], acc[1][1] + bb[1][1] };
            *(float2*)(o + col)     = v0;
            *(float2*)(o + 8 + col) = v1;
        }
        if (s_b < end) {
            float* o = out + (size_t)g_order[s_b] * NC;
            float2 v0 = { acc[0][2] + bb[0][0], acc[0][3] + bb[0][1] };
            float2 v1 = { acc[1][2] + bb[1][0], acc[1][3] + bb[1][1] };
            *(float2*)(o + col)     = v0;
            *(float2*)(o + 8 + col) = v1;
        }
    }
}

// ---------------- launch ----------------
extern "C" void kernel_launch(void* const* d_in, const int* in_sizes, int n_in,
                              void* d_out, int out_size) {
    const float* x   = (const float*)d_in[0];
    const int*   qid = (const int*)d_in[1];
    const int*   cor = (const int*)d_in[2];
    const float* W1  = (const float*)d_in[3];
    const float* b1  = (const float*)d_in[4];
    const float* W2  = (const float*)d_in[5];
    const float* b2  = (const float*)d_in[6];
    const float* Wh  = (const float*)d_in[7];
    const float* bh  = (const float*)d_in[8];
    float* out = (float*)d_out;

    cudaFuncSetAttribute(trunk_kernel, cudaFuncAttributeMaxDynamicSharedMemorySize, FUSED_SMEM);
    cudaFuncSetAttribute(heads_kernel, cudaFuncAttributeMaxDynamicSharedMemorySize, HEADS_SMEM);

    // order chosen so trunk_kernel is the 4th launch (profiler window)
    zero_kernel<<<(NHEADS + 255) / 256, 256>>>();
    hist_kernel<<<(B_TOTAL + 255) / 256, 256>>>(qid, cor);
    prep_kernel<<<(D_H * KPAD1 + D_H * D_H + 255) / 256, 256>>>(W1, W2);
    trunk_kernel<<<B_TOTAL / 64, 256, FUSED_SMEM>>>(x, b1, b2);
    scan_kernel<<<1, 1024>>>();
    scatter_kernel<<<(B_TOTAL + 255) / 256, 256>>>(qid, cor);
    heads_kernel<<<NHEADS / 8, 256, HEADS_SMEM>>>(Wh, bh, out);
}

// round 11
// speedup vs baseline: 3.2770x; 1.0283x over previous
#include <cuda_runtime.h>
#include <cuda_fp16.h>
#include <cstdint>
#include <cstddef>

// ---------------- problem constants ----------------
#define B_TOTAL 131072
#define D_INPUT 385
#define D_H     192
#define NQ      1000
#define NHEADS  2000
#define NC      16

#define KPAD1   448            // 7 chunks of 64
#define NCH1    7
#define NCH2    3
#define PA      72             // smem pitch (halves); 144B row stride -> LDSM banks 4r, conflict-free
#define THR     384            // 12 warps

// ---------------- scratch (device globals: allocation-free) ----------------
__device__ uint32_t g_feat16[(size_t)B_TOTAL * 96];  // trunk output fp16, 50 MB
__device__ __half   g_W1h[D_H * KPAD1];              // W1^T fp16 [n][448], zero-padded
__device__ __half   g_W2h[D_H * D_H];                // W2^T fp16 [n][192]
__device__ int      g_cnt[NHEADS];
__device__ int      g_off[NHEADS + 1];
__device__ int      g_rank[B_TOTAL];
__device__ int      g_order[B_TOTAL];

// ---------------- PTX helpers ----------------
#define CP16(dst, src) \
    asm volatile("cp.async.cg.shared.global [%0], [%1], 16;" \
                 :: "r"(dst), "l"(__cvta_generic_to_global((const void*)(src))))
#define CP_COMMIT() asm volatile("cp.async.commit_group;" ::: "memory")
#define CP_WAIT0()  asm volatile("cp.async.wait_group 0;" ::: "memory")

__device__ __forceinline__ void ldsm4(uint32_t r[4], uint32_t addr) {
    asm volatile("ldmatrix.sync.aligned.m8n8.x4.shared.b16 {%0,%1,%2,%3}, [%4];"
        : "=r"(r[0]), "=r"(r[1]), "=r"(r[2]), "=r"(r[3]) : "r"(addr));
}

__device__ __forceinline__ void mma16(float c[4], uint32_t a0, uint32_t a1,
                                      uint32_t a2, uint32_t a3, uint32_t b0, uint32_t b1) {
    asm volatile(
        "mma.sync.aligned.m16n8k16.row.col.f32.f16.f16.f32 "
        "{%0,%1,%2,%3}, {%4,%5,%6,%7}, {%8,%9}, {%0,%1,%2,%3};\n"
        : "+f"(c[0]), "+f"(c[1]), "+f"(c[2]), "+f"(c[3])
        : "r"(a0), "r"(a1), "r"(a2), "r"(a3), "r"(b0), "r"(b1));
}

// ---------------- prep: W1/W2 -> transposed fp16 (plain layout) ----------------
__global__ void prep_kernel(const float* __restrict__ W1, const float* __restrict__ W2) {
    int i = blockIdx.x * blockDim.x + threadIdx.x;
    const int T1 = D_H * KPAD1;
    if (i < T1) {
        int n = i / KPAD1, k = i - n * KPAD1;
        float v = (k < D_INPUT) ? W1[(size_t)k * D_H + n] : 0.f;
        g_W1h[i] = __float2half_rn(v);
    } else {
        int j = i - T1;
        if (j < D_H * D_H) {
            int n = j / D_H, k = j - n * D_H;
            g_W2h[j] = __float2half_rn(W2[(size_t)k * D_H + n]);
        }
    }
}

// ---------------- fused trunk, K64 chunks, 12 warps ----------------
// 384 threads = 12 warps: wm = wid&1 (M, 32 rows), wn = wid>>1 (N, 32 cols).
// CTA tile 64x192, 2 CTAs/SM = 24 warps/SM. ldmatrix.x4 + fp16 m16n8k16.
struct Frag { float c[2][4][4]; };

__device__ __forceinline__ void compute_part(uint32_t abase, uint32_t bbase,
                                             Frag& f, int wm, int wn, int lane,
                                             int g0, int g1)
{
    const int arow = ((lane >> 3) & 1) * 8 + (lane & 7);
    const int ak   = (lane >> 4) * 8;
    const int bn   = ((lane >> 4) & 1) * 8 + (lane & 7);
    const int bk   = ((lane >> 3) & 1) * 8;
    #pragma unroll
    for (int g = g0; g <= g1; g++) {
        uint32_t a[2][4], b[2][4];
        #pragma unroll
        for (int mt = 0; mt < 2; mt++)
            ldsm4(a[mt], abase + (uint32_t)(((wm * 32 + mt * 16 + arow) * PA + g * 16 + ak) * 2));
        #pragma unroll
        for (int p = 0; p < 2; p++)
            ldsm4(b[p], bbase + (uint32_t)(((wn * 32 + p * 16 + bn) * PA + g * 16 + bk) * 2));
        #pragma unroll
        for (int mt = 0; mt < 2; mt++)
            #pragma unroll
            for (int nt = 0; nt < 4; nt++)
                mma16(f.c[mt][nt], a[mt][0], a[mt][1], a[mt][2], a[mt][3],
                      b[nt >> 1][(nt & 1) * 2], b[nt >> 1][(nt & 1) * 2 + 1]);
    }
}

// smem layout (bytes): A0 @0 (9216), A1 @9216, B0 @18432 (27648), B1 @46080,
//                      H blocks @73728 (3 x 9216) -> total 101376 (2 CTAs/SM)
#define SM_A(b)  ((b) * 9216)
#define SM_B(b)  (18432 + (b) * 27648)
#define SM_H(c)  (73728 + (c) * 9216)
#define FUSED_SMEM 101376

__global__ void __launch_bounds__(THR, 2) trunk_kernel(
    const float* __restrict__ x, const float* __restrict__ b1, const float* __restrict__ b2)
{
    extern __shared__ char sm[];
    const uint32_t sb = (uint32_t)__cvta_generic_to_shared(sm);
    const int tid  = threadIdx.x;
    const int lane = tid & 31;
    const int wid  = tid >> 5;
    const int wm   = wid & 1, wn = wid >> 1;     // wn 0..5
    const int row0 = blockIdx.x * 64;
    const int myk   = tid & 63;                  // k within chunk for A loads
    const int rbase = tid >> 6;                  // row base (0..5), rows rbase + 6t

    Frag f;
    #pragma unroll
    for (int mt = 0; mt < 2; mt++)
        #pragma unroll
        for (int nt = 0; nt < 4; nt++)
            #pragma unroll
            for (int q = 0; q < 4; q++) f.c[mt][nt][q] = 0.f;

    // ================= phase 1: h = relu(x @ W1 + b1) =================
    // prologue: B0 (192x64 fp16 = 1536 segs, 4/thread), A0 via LDG+convert+STS
    {
        #pragma unroll
        for (int t = 0; t < 4; t++) {
            const int i = tid + t * THR, n = i >> 3, j = i & 7;
            CP16(sb + SM_B(0) + (uint32_t)(n * 144 + j * 16),
                 g_W1h + n * KPAD1 + j * 8);
        }
        CP_COMMIT();
    }
    {
        __half* Ah = (__half*)(sm + SM_A(0));
        const bool kv = (myk < D_INPUT);
        #pragma unroll
        for (int t = 0; t < 11; t++) {
            const int r = rbase + t * 6;
            if (r < 64) {
                float v = kv ? __ldg(&x[(size_t)(row0 + r) * D_INPUT + myk]) : 0.f;
                Ah[r * PA + myk] = __float2half_rn(v);
            }
        }
    }
    CP_WAIT0();
    __syncthreads();

    for (int c = 0; c < NCH1; c++) {
        const int nx = c + 1;
        float xa[6];
        const int k = nx * 64 + myk;
        const bool kv = (k < D_INPUT);
        if (nx < NCH1) {
            const uint32_t bdst = sb + SM_B(nx & 1);
            #pragma unroll
            for (int t = 0; t < 4; t++) {
                const int i = tid + t * THR, n = i >> 3, j = i & 7;
                CP16(bdst + (uint32_t)(n * 144 + j * 16),
                     g_W1h + n * KPAD1 + nx * 64 + j * 8);
            }
            CP_COMMIT();
            #pragma unroll
            for (int t = 0; t < 6; t++) {        // rows rbase..rbase+30, all < 64
                const int r = rbase + t * 6;
                xa[t] = kv ? __ldg(&x[(size_t)(row0 + r) * D_INPUT + k]) : 0.f;
            }
        }
        compute_part(sb + SM_A(c & 1), sb + SM_B(c & 1), f, wm, wn, lane, 0, 1);
        if (nx < NCH1) {
            __half* Ad = (__half*)(sm + SM_A(nx & 1));
            #pragma unroll
            for (int t = 0; t < 6; t++) {
                const int r = rbase + t * 6;
                Ad[r * PA + myk] = __float2half_rn(xa[t]);
            }
            #pragma unroll
            for (int t = 0; t < 5; t++) {        // rows rbase+36..rbase+60, guard < 64
                const int r = rbase + (t + 6) * 6;
                xa[t] = (kv && r < 64) ? __ldg(&x[(size_t)(row0 + r) * D_INPUT + k]) : 0.f;
            }
        }
        compute_part(sb + SM_A(c & 1), sb + SM_B(c & 1), f, wm, wn, lane, 2, 3);
        if (nx < NCH1) {
            __half* Ad = (__half*)(sm + SM_A(nx & 1));
            #pragma unroll
            for (int t = 0; t < 5; t++) {
                const int r = rbase + (t + 6) * 6;
                if (r < 64) Ad[r * PA + myk] = __float2half_rn(xa[t]);
            }
            CP_WAIT0();
        }
        __syncthreads();
    }

    // ---- prefetch W2 chunk 0 into B0 (overlaps epilogue 1) ----
    {
        #pragma unroll
        for (int t = 0; t < 4; t++) {
            const int i = tid + t * THR, n = i >> 3, j = i & 7;
            CP16(sb + SM_B(0) + (uint32_t)(n * 144 + j * 16),
                 g_W2h + n * D_H + j * 8);
        }
        CP_COMMIT();
    }

    // ---- epilogue 1: H blocks = fp16(relu(c + b1)) in smem ----
    #pragma unroll
    for (int mt = 0; mt < 2; mt++) {
        const int r = wm * 32 + mt * 16 + (lane >> 2);
        #pragma unroll
        for (int nt = 0; nt < 4; nt++) {
            const int n = wn * 32 + nt * 8 + 2 * (lane & 3);
            const float bb0 = __ldg(&b1[n]), bb1 = __ldg(&b1[n + 1]);
            __half2 v0 = __floats2half2_rn(fmaxf(f.c[mt][nt][0] + bb0, 0.f),
                                           fmaxf(f.c[mt][nt][1] + bb1, 0.f));
            __half2 v1 = __floats2half2_rn(fmaxf(f.c[mt][nt][2] + bb0, 0.f),
                                           fmaxf(f.c[mt][nt][3] + bb1, 0.f));
            const uint32_t off = (uint32_t)(SM_H(n >> 6) + (r * PA + (n & 63)) * 2);
            *(uint32_t*)(sm + off)            = *(uint32_t*)&v0;
            *(uint32_t*)(sm + off + PA * 16)  = *(uint32_t*)&v1;   // +8 rows
        }
    }

    #pragma unroll
    for (int mt = 0; mt < 2; mt++)
        #pragma unroll
        for (int nt = 0; nt < 4; nt++)
            #pragma unroll
            for (int q = 0; q < 4; q++) f.c[mt][nt][q] = 0.f;

    CP_WAIT0();
    __syncthreads();

    // ================= phase 2: feat = relu(H @ W2 + b2) =================
    for (int c = 0; c < NCH2; c++) {
        const int nx = c + 1;
        if (nx < NCH2) {
            const uint32_t bdst = sb + SM_B(nx & 1);
            #pragma unroll
            for (int t = 0; t < 4; t++) {
                const int i = tid + t * THR, n = i >> 3, j = i & 7;
                CP16(bdst + (uint32_t)(n * 144 + j * 16),
                     g_W2h + n * D_H + nx * 64 + j * 8);
            }
            CP_COMMIT();
        }
        compute_part(sb + SM_H(c), sb + SM_B(c & 1), f, wm, wn, lane, 0, 3);
        if (nx < NCH2) CP_WAIT0();
        __syncthreads();
    }

    // ---- epilogue 2: g_feat16 = fp16(relu(c + b2)) ----
    #pragma unroll
    for (int mt = 0; mt < 2; mt++) {
        const int r = row0 + wm * 32 + mt * 16 + (lane >> 2);
        #pragma unroll
        for (int nt = 0; nt < 4; nt++) {
            const int n = wn * 32 + nt * 8 + 2 * (lane & 3);
            const float bb0 = __ldg(&b2[n]), bb1 = __ldg(&b2[n + 1]);
            __half2 v0 = __floats2half2_rn(fmaxf(f.c[mt][nt][0] + bb0, 0.f),
                                           fmaxf(f.c[mt][nt][1] + bb1, 0.f));
            __half2 v1 = __floats2half2_rn(fmaxf(f.c[mt][nt][2] + bb0, 0.f),
                                           fmaxf(f.c[mt][nt][3] + bb1, 0.f));
            g_feat16[(size_t)r * 96 + (n >> 1)]       = *(uint32_t*)&v0;
            g_feat16[(size_t)(r + 8) * 96 + (n >> 1)] = *(uint32_t*)&v1;
        }
    }
}

// ---------------- binning: zero -> hist(+rank) -> scan -> scatter(no atomics) ----------------
__global__ void zero_kernel() {
    int i = blockIdx.x * blockDim.x + threadIdx.x;
    if (i < NHEADS) g_cnt[i] = 0;
}

__global__ void hist_kernel(const int* __restrict__ qid, const int* __restrict__ cor) {
    int b = blockIdx.x * blockDim.x + threadIdx.x;
    if (b < B_TOTAL) {
        int h = qid[b] + cor[b] * NQ;
        g_rank[b] = atomicAdd(&g_cnt[h], 1);
    }
}

__global__ void scan_kernel() {
    __shared__ int s[2048];
    const int t = threadIdx.x;
    s[t]        = (t < NHEADS) ? g_cnt[t] : 0;
    s[t + 1024] = (t + 1024 < NHEADS) ? g_cnt[t + 1024] : 0;
    __syncthreads();
    for (int d = 1; d < 2048; d <<= 1) {
        int v0 = s[t], v1 = s[t + 1024];
        int a0 = (t >= d) ? s[t - d] : 0;
        int a1 = (t + 1024 >= d) ? s[t + 1024 - d] : 0;
        __syncthreads();
        s[t] = v0 + a0;
        s[t + 1024] = v1 + a1;
        __syncthreads();
    }
    if (t < NHEADS)          { int e = (t == 0) ? 0 : s[t - 1]; g_off[t] = e; }
    if (t + 1024 < NHEADS)   { g_off[t + 1024] = s[t + 1023]; }
    if (t == 0) g_off[NHEADS] = s[NHEADS - 1];
}

__global__ void scatter_kernel(const int* __restrict__ qid, const int* __restrict__ cor) {
    int b = blockIdx.x * blockDim.x + threadIdx.x;
    if (b < B_TOTAL) {
        int h = qid[b] + cor[b] * NQ;
        g_order[g_off[h] + g_rank[b]] = b;
    }
}

// ---------------- routed heads: one WARP per head group, tensor-core GEMM ----------------
#define HROW_B   400
#define H_WARP_B 6400
#define HEADS_SMEM (8 * H_WARP_B)

__global__ void __launch_bounds__(256, 2) heads_kernel(
    const float* __restrict__ Wh, const float* __restrict__ bh, float* __restrict__ out)
{
    extern __shared__ char sm[];
    const int tid  = threadIdx.x;
    const int lane = tid & 31;
    const int wid  = tid >> 5;
    const int g    = blockIdx.x * 8 + wid;
    const uint32_t wbase = (uint32_t)__cvta_generic_to_shared(sm) + (uint32_t)(wid * H_WARP_B);

    const int start = g_off[g], end = g_off[g + 1];
    if (start >= end) return;

    uint32_t bw[48];
    {
        const int n_lo = lane >> 2, q2 = 2 * (lane & 3);
        #pragma unroll
        for (int kk = 0; kk < 12; kk++) {
            #pragma unroll
            for (int p = 0; p < 2; p++) {
                const float* src = Wh + ((size_t)g * NC + p * 8 + n_lo) * D_H + kk * 16 + q2;
                const float2 lo = *(const float2*)src;
                const float2 hi = *(const float2*)(src + 8);
                const __half2 l2 = __floats2half2_rn(lo.x, lo.y);
                const __half2 h2 = __floats2half2_rn(hi.x, hi.y);
                bw[kk * 4 + p * 2]     = *(const uint32_t*)&l2;
                bw[kk * 4 + p * 2 + 1] = *(const uint32_t*)&h2;
            }
        }
    }
    float bb[2][2];
    {
        const int col = 2 * (lane & 3);
        bb[0][0] = __ldg(&bh[g * NC + col]);
        bb[0][1] = __ldg(&bh[g * NC + col + 1]);
        bb[1][0] = __ldg(&bh[g * NC + 8 + col]);
        bb[1][1] = __ldg(&bh[g * NC + 8 + col + 1]);
    }

    const int myrow = lane & 15;
    const int seg0  = (lane >> 4) * 12;
    const int arow  = ((lane >> 3) & 1) * 8 + (lane & 7);
    const int ak2   = ((lane >> 4) * 8) * 2;
    const int r0    = lane >> 2, col = 2 * (lane & 3);

    for (int s0 = start; s0 < end; s0 += 16) {
        {
            const int sIdx = s0 + myrow;
            const int sC = (sIdx < end) ? sIdx : (end - 1);
            const char* src = (const char*)(g_feat16 + (size_t)g_order[sC] * 96);
            const uint32_t dst = wbase + (uint32_t)(myrow * HROW_B);
            #pragma unroll
            for (int t = 0; t < 12; t++) {
                const int j = seg0 + t;
                CP16(dst + (uint32_t)(j * 16), src + j * 16);
            }
            CP_COMMIT();
            CP_WAIT0();
            __syncwarp();
        }

        float acc[2][4];
        #pragma unroll
        for (int p = 0; p < 2; p++)
            #pragma unroll
            for (int q = 0; q < 4; q++) acc[p][q] = 0.f;

        #pragma unroll
        for (int kk = 0; kk < 12; kk++) {
            uint32_t a[4];
            ldsm4(a, wbase + (uint32_t)(arow * HROW_B + kk * 32) + (uint32_t)ak2);
            mma16(acc[0], a[0], a[1], a[2], a[3], bw[kk * 4],     bw[kk * 4 + 1]);
            mma16(acc[1], a[0], a[1], a[2], a[3], bw[kk * 4 + 2], bw[kk * 4 + 3]);
        }
        __syncwarp();

        const int s_a = s0 + r0, s_b = s0 + r0 + 8;
        if (s_a < end) {
            float* o = out + (size_t)g_order[s_a] * NC;
            float2 v0 = { acc[0][0] + bb[0][0], acc[0][1] + bb[0][1] };
            float2 v1 = { acc[1][0] + bb[1][0], acc[1][1] + bb[1][1] };
            *(float2*)(o + col)     = v0;
            *(float2*)(o + 8 + col) = v1;
        }
        if (s_b < end) {
            float* o = out + (size_t)g_order[s_b] * NC;
            float2 v0 = { acc[0][2] + bb[0][0], acc[0][3] + bb[0][1] };
            float2 v1 = { acc[1][2] + bb[1][0], acc[1][3] + bb[1][1] };
            *(float2*)(o + col)     = v0;
            *(float2*)(o + 8 + col) = v1;
        }
    }
}

// ---------------- launch ----------------
extern "C" void kernel_launch(void* const* d_in, const int* in_sizes, int n_in,
                              void* d_out, int out_size) {
    const float* x   = (const float*)d_in[0];
    const int*   qid = (const int*)d_in[1];
    const int*   cor = (const int*)d_in[2];
    const float* W1  = (const float*)d_in[3];
    const float* b1  = (const float*)d_in[4];
    const float* W2  = (const float*)d_in[5];
    const float* b2  = (const float*)d_in[6];
    const float* Wh  = (const float*)d_in[7];
    const float* bh  = (const float*)d_in[8];
    float* out = (float*)d_out;

    cudaFuncSetAttribute(trunk_kernel, cudaFuncAttributeMaxDynamicSharedMemorySize, FUSED_SMEM);
    cudaFuncSetAttribute(heads_kernel, cudaFuncAttributeMaxDynamicSharedMemorySize, HEADS_SMEM);

    // order chosen so trunk_kernel is the 4th launch (profiler window)
    zero_kernel<<<(NHEADS + 255) / 256, 256>>>();
    hist_kernel<<<(B_TOTAL + 255) / 256, 256>>>(qid, cor);
    prep_kernel<<<(D_H * KPAD1 + D_H * D_H + 255) / 256, 256>>>(W1, W2);
    trunk_kernel<<<B_TOTAL / 64, THR, FUSED_SMEM>>>(x, b1, b2);
    scan_kernel<<<1, 1024>>>();
    scatter_kernel<<<(B_TOTAL + 255) / 256, 256>>>(qid, cor);
    heads_kernel<<<NHEADS / 8, 256, HEADS_SMEM>>>(Wh, bh, out);
}